// round 10
// baseline (speedup 1.0000x reference)
#include <cuda_runtime.h>
#include <cuda_bf16.h>
#include <math.h>
#include <stdint.h>

// Problem constants
#define BATCH 8
#define LV    16384
#define LVH   8192
#define NNODE 32767
#define NINT  16383
#define DH    256
#define NC    1024
#define TOTAL_ROWS (BATCH * NNODE)   // 262136

// GEMM tiling
#define TBM 128
#define TBN 128
#define NSTAGE 4
#define STG_BYTES 32768       // Ah(8K) Al(8K) Bh(8K) Bl(8K)
#define SMEM_DYN (NSTAGE * STG_BYTES)

// ---------------- scratch (device globals) ----------------------------------
__device__ __nv_bfloat16 g_Wh[NC * 256];
__device__ __nv_bfloat16 g_Wl[NC * 256];
__device__ __nv_bfloat16 g_Uh[NC * 256];
__device__ __nv_bfloat16 g_Ul[NC * 256];
__device__ __nv_bfloat16 g_xh[(size_t)TOTAL_ROWS * 256];
__device__ __nv_bfloat16 g_xl[(size_t)TOTAL_ROWS * 256];
__device__ __nv_bfloat16 g_hh[(size_t)TOTAL_ROWS * 256];
__device__ __nv_bfloat16 g_hl[(size_t)TOTAL_ROWS * 256];
__device__ float g_xproj[(size_t)TOTAL_ROWS * NC];
__device__ float g_c[(size_t)TOTAL_ROWS * 256];
__device__ float g_R[(size_t)BATCH * LV * NC];

__device__ __forceinline__ float sigm(float x) { return 1.0f / (1.0f + expf(-x)); }

// ---------------- PTX helpers ------------------------------------------------
__device__ __forceinline__ uint32_t smem_u32(const void* p) {
    uint32_t a;
    asm("{ .reg .u64 t; cvta.to.shared.u64 t, %1; cvt.u32.u64 %0, t; }" : "=r"(a) : "l"(p));
    return a;
}
__device__ __forceinline__ void ldsm4(uint32_t& r0, uint32_t& r1, uint32_t& r2, uint32_t& r3, uint32_t addr) {
    asm volatile("ldmatrix.sync.aligned.m8n8.x4.shared.b16 {%0,%1,%2,%3},[%4];"
                 : "=r"(r0), "=r"(r1), "=r"(r2), "=r"(r3) : "r"(addr));
}
__device__ __forceinline__ void mma16816(float* c, const uint32_t* a, uint32_t b0, uint32_t b1) {
    asm volatile("mma.sync.aligned.m16n8k16.row.col.f32.bf16.bf16.f32 "
                 "{%0,%1,%2,%3},{%4,%5,%6,%7},{%8,%9},{%0,%1,%2,%3};"
                 : "+f"(c[0]), "+f"(c[1]), "+f"(c[2]), "+f"(c[3])
                 : "r"(a[0]), "r"(a[1]), "r"(a[2]), "r"(a[3]), "r"(b0), "r"(b1));
}
__device__ __forceinline__ void cp16(uint32_t dst, const void* src, int srcsz) {
    asm volatile("cp.async.cg.shared.global [%0], [%1], 16, %2;" :: "r"(dst), "l"(src), "r"(srcsz) : "memory");
}
#define CP_COMMIT() asm volatile("cp.async.commit_group;" ::: "memory")
#define CP_WAIT(n)  asm volatile("cp.async.wait_group %0;" :: "n"(n) : "memory")

__device__ __forceinline__ uint32_t swz(int r, int c) {
    return (uint32_t)(r * 64 + ((c ^ ((r >> 1) & 3)) << 4));
}
__device__ __forceinline__ void split_store4(__nv_bfloat16* hi, __nv_bfloat16* lo, float4 v) {
    __nv_bfloat16 a = __float2bfloat16_rn(v.x), b = __float2bfloat16_rn(v.y),
                  c = __float2bfloat16_rn(v.z), e = __float2bfloat16_rn(v.w);
    *(__nv_bfloat162*)(hi)     = __nv_bfloat162(a, b);
    *(__nv_bfloat162*)(hi + 2) = __nv_bfloat162(c, e);
    *(__nv_bfloat162*)(lo)     = __nv_bfloat162(__float2bfloat16_rn(v.x - __bfloat162float(a)),
                                                __float2bfloat16_rn(v.y - __bfloat162float(b)));
    *(__nv_bfloat162*)(lo + 2) = __nv_bfloat162(__float2bfloat16_rn(v.z - __bfloat162float(c)),
                                                __float2bfloat16_rn(v.w - __bfloat162float(e)));
}
__device__ __forceinline__ float4 add4(float4 a, float4 b) {
    return make_float4(a.x + b.x, a.y + b.y, a.z + b.z, a.w + b.w);
}

// ---------------- weight packing ---------------------------------------------
__global__ void pack_weights(const float* __restrict__ W_iou, const float* __restrict__ W_f,
                             const float* __restrict__ U_iou, const float* __restrict__ U_f) {
    int idx = blockIdx.x * blockDim.x + threadIdx.x;
    if (idx >= NC * 256) return;
    int j = idx / 256, k = idx % 256;
    float wv = (j < 768) ? W_iou[k * 768 + j] : W_f[k * 256 + (j - 768)];
    float uv = (j < 768) ? U_iou[k * 768 + j] : U_f[k * 256 + (j - 768)];
    __nv_bfloat16 wh = __float2bfloat16_rn(wv);
    g_Wh[idx] = wh;
    g_Wl[idx] = __float2bfloat16_rn(wv - __bfloat162float(wh));
    __nv_bfloat16 uh = __float2bfloat16_rn(uv);
    g_Uh[idx] = uh;
    g_Ul[idx] = __float2bfloat16_rn(uv - __bfloat162float(uh));
}

// ---------------- x hi/lo split ----------------------------------------------
__global__ void split_x(const float* __restrict__ x) {
    size_t i = (size_t)blockIdx.x * blockDim.x + threadIdx.x;
    const size_t n4 = (size_t)TOTAL_ROWS * 256 / 4;
    if (i >= n4) return;
    float4 v = ((const float4*)x)[i];
    split_store4(g_xh + 4 * i, g_xl + 4 * i, v);
}

// ---------------- mma.sync GEMM: C[M x 1024] = A[M x 256] @ W ----------------
// CTA tile 128x128x32, warp tile 64x32, 3-term bf16 split, 4-stage pipeline.
__global__ __launch_bounds__(256, 1)
void gemm_mma(int asel, int wsel, int csel, int M, int rpb, int row_off, int node_stride)
{
    extern __shared__ char smem[];
    const uint32_t sb = smem_u32(smem);
    const int tid = threadIdx.x, wid = tid >> 5, lane = tid & 31;
    const int wm = wid >> 2, wn = wid & 3;
    const int row0 = blockIdx.y * TBM;
    const int col0 = blockIdx.x * TBN;

    const __nv_bfloat16* Ahg = asel ? g_hh : g_xh;
    const __nv_bfloat16* Alg = asel ? g_hl : g_xl;
    const __nv_bfloat16* Bhg = wsel ? g_Uh : g_Wh;
    const __nv_bfloat16* Blg = wsel ? g_Ul : g_Wl;
    float* C = csel ? g_R : g_xproj;

    const int lr = tid >> 1;
    const int c2 = (tid & 1) * 2;
    size_t aoff; int asz;
    {
        int m = row0 + lr;
        if (m < M) {
            int bb = m / rpb, loc = m - bb * rpb;
            aoff = ((size_t)bb * node_stride + (size_t)(row_off + loc)) * 256;
            asz = 16;
        } else { aoff = 0; asz = 0; }
    }
    const size_t boff = (size_t)(col0 + lr) * 256;
    const uint32_t s0 = swz(lr, c2), s1 = swz(lr, c2 + 1);

#define LOAD_CHUNK(kc, st) do {                                               \
        uint32_t bs = sb + (uint32_t)(st) * STG_BYTES;                        \
        int kg = (kc) * 32;                                                   \
        cp16(bs + s0,          Ahg + aoff + kg + c2 * 8,       asz);          \
        cp16(bs + s1,          Ahg + aoff + kg + c2 * 8 + 8,   asz);          \
        cp16(bs + 8192 + s0,   Alg + aoff + kg + c2 * 8,       asz);          \
        cp16(bs + 8192 + s1,   Alg + aoff + kg + c2 * 8 + 8,   asz);          \
        cp16(bs + 16384 + s0,  Bhg + boff + kg + c2 * 8,       16);           \
        cp16(bs + 16384 + s1,  Bhg + boff + kg + c2 * 8 + 8,   16);           \
        cp16(bs + 24576 + s0,  Blg + boff + kg + c2 * 8,       16);           \
        cp16(bs + 24576 + s1,  Blg + boff + kg + c2 * 8 + 8,   16);           \
        CP_COMMIT();                                                          \
    } while (0)

    float acc[4][4][4];
#pragma unroll
    for (int mt = 0; mt < 4; mt++)
#pragma unroll
        for (int nt = 0; nt < 4; nt++)
#pragma unroll
            for (int e = 0; e < 4; e++) acc[mt][nt][e] = 0.0f;

#define COMPUTE_CHUNK(st) do {                                                \
        uint32_t cb = sb + (uint32_t)(st) * STG_BYTES;                        \
        _Pragma("unroll")                                                     \
        for (int ks = 0; ks < 2; ks++) {                                      \
            uint32_t ah[4][4], al[4][4];                                      \
            int cch = ks * 2 + (lane >> 4);                                   \
            _Pragma("unroll")                                                 \
            for (int mt = 0; mt < 4; mt++) {                                  \
                int mr = wm * 64 + mt * 16 + (lane & 15);                     \
                uint32_t ad = cb + swz(mr, cch);                              \
                ldsm4(ah[mt][0], ah[mt][1], ah[mt][2], ah[mt][3], ad);        \
                ldsm4(al[mt][0], al[mt][1], al[mt][2], al[mt][3], ad + 8192); \
            }                                                                 \
            _Pragma("unroll")                                                 \
            for (int nt2 = 0; nt2 < 2; nt2++) {                               \
                int nr = wn * 32 + nt2 * 16 + (lane & 15);                    \
                uint32_t bd = cb + 16384 + swz(nr, cch);                      \
                uint32_t bh[4], bl[4];                                        \
                ldsm4(bh[0], bh[1], bh[2], bh[3], bd);                        \
                ldsm4(bl[0], bl[1], bl[2], bl[3], bd + 8192);                 \
                _Pragma("unroll")                                             \
                for (int mt = 0; mt < 4; mt++) {                              \
                    mma16816(acc[mt][nt2 * 2],     ah[mt], bh[0], bh[2]);     \
                    mma16816(acc[mt][nt2 * 2],     ah[mt], bl[0], bl[2]);     \
                    mma16816(acc[mt][nt2 * 2],     al[mt], bh[0], bh[2]);     \
                    mma16816(acc[mt][nt2 * 2 + 1], ah[mt], bh[1], bh[3]);     \
                    mma16816(acc[mt][nt2 * 2 + 1], ah[mt], bl[1], bl[3]);     \
                    mma16816(acc[mt][nt2 * 2 + 1], al[mt], bh[1], bh[3]);     \
                }                                                             \
            }                                                                 \
        }                                                                     \
    } while (0)

    // 4-stage pipeline, single barrier per chunk.
    LOAD_CHUNK(0, 0);
    LOAD_CHUNK(1, 1);
    LOAD_CHUNK(2, 2);

#pragma unroll 1
    for (int kc = 0; kc < 5; kc++) {
        CP_WAIT(2);
        __syncthreads();
        COMPUTE_CHUNK(kc & 3);
        LOAD_CHUNK(kc + 3, (kc + 3) & 3);
    }
    CP_WAIT(2); __syncthreads(); COMPUTE_CHUNK(1);   // chunk 5 -> stage 1
    CP_WAIT(1); __syncthreads(); COMPUTE_CHUNK(2);   // chunk 6 -> stage 2
    CP_WAIT(0); __syncthreads(); COMPUTE_CHUNK(3);   // chunk 7 -> stage 3

    // epilogue
#pragma unroll
    for (int mt = 0; mt < 4; mt++) {
        int r_lo = row0 + wm * 64 + mt * 16 + (lane >> 2);
        int r_hi = r_lo + 8;
#pragma unroll
        for (int nt = 0; nt < 4; nt++) {
            int cc = col0 + wn * 32 + nt * 8 + 2 * (lane & 3);
            if (r_lo < M)
                *(float2*)(&C[(size_t)r_lo * NC + cc]) = make_float2(acc[mt][nt][0], acc[mt][nt][1]);
            if (r_hi < M)
                *(float2*)(&C[(size_t)r_hi * NC + cc]) = make_float2(acc[mt][nt][2], acc[mt][nt][3]);
        }
    }
#undef LOAD_CHUNK
#undef COMPUTE_CHUNK
}

// ---------------- leaf elementwise (float4) ----------------------------------
__global__ void leaf_v4(const float* __restrict__ b_iou) {
    int gid = blockIdx.x * blockDim.x + threadIdx.x;
    const int total = BATCH * LV * 64;
    if (gid >= total) return;
    int d = (gid & 63) << 2;
    int rest = gid >> 6;
    int k = rest & (LV - 1);
    int bb = rest >> 14;
    size_t row = (size_t)bb * NNODE + NINT + k;

    float4 bi = *(const float4*)(b_iou + d);
    float4 bo = *(const float4*)(b_iou + 256 + d);
    float4 bu = *(const float4*)(b_iou + 512 + d);

    size_t xrow = row * NC;
    float4 i4 = add4(*(const float4*)(g_xproj + xrow + d), bi);
    float4 o4 = add4(*(const float4*)(g_xproj + xrow + 256 + d), bo);
    float4 u4 = add4(*(const float4*)(g_xproj + xrow + 512 + d), bu);
    float4 c4, h4;
    c4.x = sigm(i4.x) * tanhf(u4.x); h4.x = sigm(o4.x) * tanhf(c4.x);
    c4.y = sigm(i4.y) * tanhf(u4.y); h4.y = sigm(o4.y) * tanhf(c4.y);
    c4.z = sigm(i4.z) * tanhf(u4.z); h4.z = sigm(o4.z) * tanhf(c4.z);
    c4.w = sigm(i4.w) * tanhf(u4.w); h4.w = sigm(o4.w) * tanhf(c4.w);
    size_t hrow = row * 256 + d;
    *(float4*)(g_c + hrow) = c4;
    split_store4(g_hh + hrow, g_hl + hrow, h4);
}

// ---------------- internal-level combine (float4) ----------------------------
__global__ void combine_v4(const float* __restrict__ b_iou, const float* __restrict__ b_f, int n) {
    int gid = blockIdx.x * blockDim.x + threadIdx.x;
    const int total = BATCH * n * 64;
    if (gid >= total) return;
    int d = (gid & 63) << 2;
    int rest = gid >> 6;
    int k = rest % n;
    int bb = rest / n;
    int j = n - 1 + k;
    size_t row = (size_t)bb * NNODE + j;

    size_t r0 = ((size_t)bb * 2 * n + 2 * k) * NC;
    size_t r1 = r0 + NC;

    float4 bi = *(const float4*)(b_iou + d);
    float4 bo = *(const float4*)(b_iou + 256 + d);
    float4 bu = *(const float4*)(b_iou + 512 + d);
    float4 bf = *(const float4*)(b_f + d);

    size_t xrow = row * NC;
    float4 i4 = add4(add4(*(const float4*)(g_xproj + xrow + d),
                          add4(*(const float4*)(g_R + r0 + d), *(const float4*)(g_R + r1 + d))), bi);
    float4 o4 = add4(add4(*(const float4*)(g_xproj + xrow + 256 + d),
                          add4(*(const float4*)(g_R + r0 + 256 + d), *(const float4*)(g_R + r1 + 256 + d))), bo);
    float4 u4 = add4(add4(*(const float4*)(g_xproj + xrow + 512 + d),
                          add4(*(const float4*)(g_R + r0 + 512 + d), *(const float4*)(g_R + r1 + 512 + d))), bu);
    float4 fx = add4(*(const float4*)(g_xproj + xrow + 768 + d), bf);
    float4 f0 = *(const float4*)(g_R + r0 + 768 + d);
    float4 f1 = *(const float4*)(g_R + r1 + 768 + d);

    size_t crow = ((size_t)bb * NNODE + 2 * j + 1) * 256 + d;
    float4 c0 = *(const float4*)(g_c + crow);
    float4 c1 = *(const float4*)(g_c + crow + 256);

    float4 c4, h4;
    c4.x = sigm(i4.x) * tanhf(u4.x) + sigm(fx.x + f0.x) * c0.x + sigm(fx.x + f1.x) * c1.x;
    c4.y = sigm(i4.y) * tanhf(u4.y) + sigm(fx.y + f0.y) * c0.y + sigm(fx.y + f1.y) * c1.y;
    c4.z = sigm(i4.z) * tanhf(u4.z) + sigm(fx.z + f0.z) * c0.z + sigm(fx.z + f1.z) * c1.z;
    c4.w = sigm(i4.w) * tanhf(u4.w) + sigm(fx.w + f0.w) * c0.w + sigm(fx.w + f1.w) * c1.w;
    h4.x = sigm(o4.x) * tanhf(c4.x);
    h4.y = sigm(o4.y) * tanhf(c4.y);
    h4.z = sigm(o4.z) * tanhf(c4.z);
    h4.w = sigm(o4.w) * tanhf(c4.w);

    size_t hrow = row * 256 + d;
    *(float4*)(g_c + hrow) = c4;
    split_store4(g_hh + hrow, g_hl + hrow, h4);
}

// ---------------- fused small level: one block per parent node ---------------
__global__ void level_small(const float* __restrict__ b_iou, const float* __restrict__ b_f,
                            const float* __restrict__ U_iou, const float* __restrict__ U_f,
                            int n, float* __restrict__ out) {
    __shared__ float h0s[256], h1s[256], hss[256];
    int blk = blockIdx.x;               // bb * n + k
    int bb = blk / n, k = blk - bb * n;
    int j = n - 1 + k;
    int d = threadIdx.x;

    size_t rc = ((size_t)bb * NNODE + 2 * j + 1) * 256;   // child0 row base
    float h0 = __bfloat162float(g_hh[rc + d]) + __bfloat162float(g_hl[rc + d]);
    float h1 = __bfloat162float(g_hh[rc + 256 + d]) + __bfloat162float(g_hl[rc + 256 + d]);
    h0s[d] = h0; h1s[d] = h1; hss[d] = h0 + h1;
    __syncthreads();

    float ai = 0.f, ao = 0.f, au = 0.f, af0 = 0.f, af1 = 0.f;
#pragma unroll 8
    for (int kk = 0; kk < 256; kk++) {
        float hs = hss[kk], a0 = h0s[kk], a1 = h1s[kk];
        const float* Ur = U_iou + kk * 768 + d;
        ai = fmaf(hs, Ur[0], ai);
        ao = fmaf(hs, Ur[256], ao);
        au = fmaf(hs, Ur[512], au);
        float wf = U_f[kk * 256 + d];
        af0 = fmaf(a0, wf, af0);
        af1 = fmaf(a1, wf, af1);
    }

    size_t xrow = ((size_t)bb * NNODE + j) * NC;
    float iv = g_xproj[xrow + d]       + b_iou[d]       + ai;
    float ov = g_xproj[xrow + 256 + d] + b_iou[256 + d] + ao;
    float uv = g_xproj[xrow + 512 + d] + b_iou[512 + d] + au;
    float fx = g_xproj[xrow + 768 + d] + b_f[d];
    float c0 = g_c[rc + d], c1 = g_c[rc + 256 + d];
    float cv = sigm(iv) * tanhf(uv) + sigm(fx + af0) * c0 + sigm(fx + af1) * c1;
    float hv = sigm(ov) * tanhf(cv);

    size_t hrow = ((size_t)bb * NNODE + j) * 256 + d;
    g_c[hrow] = cv;
    __nv_bfloat16 hh = __float2bfloat16_rn(hv);
    g_hh[hrow] = hh;
    g_hl[hrow] = __float2bfloat16_rn(hv - __bfloat162float(hh));

    if (n == 1) {
        out[bb * 512 + d] = hv;
        out[bb * 512 + 256 + d] = cv;
    }
}

// ---------------- launch ----------------------------------------------------
extern "C" void kernel_launch(void* const* d_in, const int* in_sizes, int n_in,
                              void* d_out, int out_size) {
    const float* x     = (const float*)d_in[0];
    const float* W_iou = (const float*)d_in[1];
    const float* b_iou = (const float*)d_in[2];
    const float* U_iou = (const float*)d_in[3];
    const float* W_f   = (const float*)d_in[4];
    const float* b_f   = (const float*)d_in[5];
    const float* U_f   = (const float*)d_in[6];
    float* out = (float*)d_out;

    cudaFuncSetAttribute(gemm_mma, cudaFuncAttributeMaxDynamicSharedMemorySize, SMEM_DYN);

    pack_weights<<<(NC * 256 + 255) / 256, 256>>>(W_iou, W_f, U_iou, U_f);
    {
        size_t n4 = (size_t)TOTAL_ROWS * 256 / 4;
        split_x<<<(unsigned)((n4 + 255) / 256), 256>>>(x);
    }

    // input projection for ALL nodes
    {
        dim3 grid(NC / TBN, (TOTAL_ROWS + TBM - 1) / TBM);
        gemm_mma<<<grid, 256, SMEM_DYN>>>(0, 0, 0, TOTAL_ROWS, TOTAL_ROWS, 0, 0);
    }

    // leaves
    leaf_v4<<<BATCH * LV * 64 / 256, 256>>>(b_iou);

    // big levels: tensor-core recurrent GEMM + combine
    for (int n = LVH; n >= 256; n >>= 1) {
        int rows = BATCH * 2 * n;
        dim3 grid(NC / TBN, (rows + TBM - 1) / TBM);
        gemm_mma<<<grid, 256, SMEM_DYN>>>(1, 1, 1, rows, 2 * n, 2 * n - 1, NNODE);
        int total = BATCH * n * 64;
        combine_v4<<<(total + 255) / 256, 256>>>(b_iou, b_f, n);
    }

    // small levels fused (n = 128 .. 1), n==1 writes out
    for (int n = 128; n >= 1; n >>= 1)
        level_small<<<BATCH * n, 256>>>(b_iou, b_f, U_iou, U_f, n, out);
}

// round 11
// speedup vs baseline: 1.1826x; 1.1826x over previous
#include <cuda_runtime.h>
#include <cuda_bf16.h>
#include <math.h>
#include <stdint.h>

// Problem constants
#define BATCH 8
#define LV    16384
#define LVH   8192
#define NNODE 32767
#define NINT  16383
#define DH    256
#define NC    1024
#define TOTAL_ROWS (BATCH * NNODE)   // 262136

// GEMM tiling (R8-proven: 3 stages, 96KB -> 2 CTAs/SM)
#define TBM 128
#define TBN 128
#define NSTAGE 3
#define STG_BYTES 32768       // Ah(8K) Al(8K) Bh(8K) Bl(8K)
#define SMEM_DYN (NSTAGE * STG_BYTES)

// ---------------- scratch (device globals) ----------------------------------
__device__ __nv_bfloat16 g_Wh[NC * 256];
__device__ __nv_bfloat16 g_Wl[NC * 256];
__device__ __nv_bfloat16 g_Uh[NC * 256];
__device__ __nv_bfloat16 g_Ul[NC * 256];
__device__ __nv_bfloat16 g_xh[(size_t)TOTAL_ROWS * 256];
__device__ __nv_bfloat16 g_xl[(size_t)TOTAL_ROWS * 256];
__device__ __nv_bfloat16 g_hh[(size_t)TOTAL_ROWS * 256];
__device__ __nv_bfloat16 g_hl[(size_t)TOTAL_ROWS * 256];
__device__ float g_xproj[(size_t)TOTAL_ROWS * NC];
__device__ float g_c[(size_t)TOTAL_ROWS * 256];
__device__ float g_R[(size_t)BATCH * LV * NC];

__device__ __forceinline__ float sigm(float x) { return 1.0f / (1.0f + expf(-x)); }

// ---------------- PTX helpers ------------------------------------------------
__device__ __forceinline__ uint32_t smem_u32(const void* p) {
    uint32_t a;
    asm("{ .reg .u64 t; cvta.to.shared.u64 t, %1; cvt.u32.u64 %0, t; }" : "=r"(a) : "l"(p));
    return a;
}
__device__ __forceinline__ void ldsm4(uint32_t& r0, uint32_t& r1, uint32_t& r2, uint32_t& r3, uint32_t addr) {
    asm volatile("ldmatrix.sync.aligned.m8n8.x4.shared.b16 {%0,%1,%2,%3},[%4];"
                 : "=r"(r0), "=r"(r1), "=r"(r2), "=r"(r3) : "r"(addr));
}
__device__ __forceinline__ void mma16816(float* c, const uint32_t* a, uint32_t b0, uint32_t b1) {
    asm volatile("mma.sync.aligned.m16n8k16.row.col.f32.bf16.bf16.f32 "
                 "{%0,%1,%2,%3},{%4,%5,%6,%7},{%8,%9},{%0,%1,%2,%3};"
                 : "+f"(c[0]), "+f"(c[1]), "+f"(c[2]), "+f"(c[3])
                 : "r"(a[0]), "r"(a[1]), "r"(a[2]), "r"(a[3]), "r"(b0), "r"(b1));
}
__device__ __forceinline__ void cp16(uint32_t dst, const void* src, int srcsz) {
    asm volatile("cp.async.cg.shared.global [%0], [%1], 16, %2;" :: "r"(dst), "l"(src), "r"(srcsz) : "memory");
}
#define CP_COMMIT() asm volatile("cp.async.commit_group;" ::: "memory")
#define CP_WAIT(n)  asm volatile("cp.async.wait_group %0;" :: "n"(n) : "memory")

__device__ __forceinline__ uint32_t swz(int r, int c) {
    return (uint32_t)(r * 64 + ((c ^ ((r >> 1) & 3)) << 4));
}
__device__ __forceinline__ void split_store4(__nv_bfloat16* hi, __nv_bfloat16* lo, float4 v) {
    __nv_bfloat16 a = __float2bfloat16_rn(v.x), b = __float2bfloat16_rn(v.y),
                  c = __float2bfloat16_rn(v.z), e = __float2bfloat16_rn(v.w);
    *(__nv_bfloat162*)(hi)     = __nv_bfloat162(a, b);
    *(__nv_bfloat162*)(hi + 2) = __nv_bfloat162(c, e);
    *(__nv_bfloat162*)(lo)     = __nv_bfloat162(__float2bfloat16_rn(v.x - __bfloat162float(a)),
                                                __float2bfloat16_rn(v.y - __bfloat162float(b)));
    *(__nv_bfloat162*)(lo + 2) = __nv_bfloat162(__float2bfloat16_rn(v.z - __bfloat162float(c)),
                                                __float2bfloat16_rn(v.w - __bfloat162float(e)));
}
__device__ __forceinline__ float4 add4(float4 a, float4 b) {
    return make_float4(a.x + b.x, a.y + b.y, a.z + b.z, a.w + b.w);
}

// ---------------- weight packing ---------------------------------------------
__global__ void pack_weights(const float* __restrict__ W_iou, const float* __restrict__ W_f,
                             const float* __restrict__ U_iou, const float* __restrict__ U_f) {
    int idx = blockIdx.x * blockDim.x + threadIdx.x;
    if (idx >= NC * 256) return;
    int j = idx / 256, k = idx % 256;
    float wv = (j < 768) ? W_iou[k * 768 + j] : W_f[k * 256 + (j - 768)];
    float uv = (j < 768) ? U_iou[k * 768 + j] : U_f[k * 256 + (j - 768)];
    __nv_bfloat16 wh = __float2bfloat16_rn(wv);
    g_Wh[idx] = wh;
    g_Wl[idx] = __float2bfloat16_rn(wv - __bfloat162float(wh));
    __nv_bfloat16 uh = __float2bfloat16_rn(uv);
    g_Uh[idx] = uh;
    g_Ul[idx] = __float2bfloat16_rn(uv - __bfloat162float(uh));
}

// ---------------- x hi/lo split ----------------------------------------------
__global__ void split_x(const float* __restrict__ x) {
    size_t i = (size_t)blockIdx.x * blockDim.x + threadIdx.x;
    const size_t n4 = (size_t)TOTAL_ROWS * 256 / 4;
    if (i >= n4) return;
    float4 v = ((const float4*)x)[i];
    split_store4(g_xh + 4 * i, g_xl + 4 * i, v);
}

// ---------------- mma.sync GEMM: C[M x 1024] = A[M x 256] @ W ----------------
// CTA tile 128x128x32, warp tile 64x32 (8 warps 2x4), 3-term bf16 split.
// Exact R8 pipeline: 3 stages, two barriers per chunk, 96KB smem (2 CTAs/SM).
__global__ __launch_bounds__(256, 2)
void gemm_mma(int asel, int wsel, int csel, int M, int rpb, int row_off, int node_stride)
{
    extern __shared__ char smem[];
    const uint32_t sb = smem_u32(smem);
    const int tid = threadIdx.x, wid = tid >> 5, lane = tid & 31;
    const int wm = wid >> 2, wn = wid & 3;
    const int row0 = blockIdx.y * TBM;
    const int col0 = blockIdx.x * TBN;

    const __nv_bfloat16* Ahg = asel ? g_hh : g_xh;
    const __nv_bfloat16* Alg = asel ? g_hl : g_xl;
    const __nv_bfloat16* Bhg = wsel ? g_Uh : g_Wh;
    const __nv_bfloat16* Blg = wsel ? g_Ul : g_Wl;
    float* C = csel ? g_R : g_xproj;

    const int lr = tid >> 1;
    const int c2 = (tid & 1) * 2;
    size_t aoff; int asz;
    {
        int m = row0 + lr;
        if (m < M) {
            int bb = m / rpb, loc = m - bb * rpb;
            aoff = ((size_t)bb * node_stride + (size_t)(row_off + loc)) * 256;
            asz = 16;
        } else { aoff = 0; asz = 0; }
    }
    const size_t boff = (size_t)(col0 + lr) * 256;
    const uint32_t s0 = swz(lr, c2), s1 = swz(lr, c2 + 1);

#define LOAD_CHUNK(kc, st) do {                                               \
        uint32_t bs = sb + (uint32_t)(st) * STG_BYTES;                        \
        int kg = (kc) * 32;                                                   \
        cp16(bs + s0,          Ahg + aoff + kg + c2 * 8,       asz);          \
        cp16(bs + s1,          Ahg + aoff + kg + c2 * 8 + 8,   asz);          \
        cp16(bs + 8192 + s0,   Alg + aoff + kg + c2 * 8,       asz);          \
        cp16(bs + 8192 + s1,   Alg + aoff + kg + c2 * 8 + 8,   asz);          \
        cp16(bs + 16384 + s0,  Bhg + boff + kg + c2 * 8,       16);           \
        cp16(bs + 16384 + s1,  Bhg + boff + kg + c2 * 8 + 8,   16);           \
        cp16(bs + 24576 + s0,  Blg + boff + kg + c2 * 8,       16);           \
        cp16(bs + 24576 + s1,  Blg + boff + kg + c2 * 8 + 8,   16);           \
        CP_COMMIT();                                                          \
    } while (0)

    float acc[4][4][4];
#pragma unroll
    for (int mt = 0; mt < 4; mt++)
#pragma unroll
        for (int nt = 0; nt < 4; nt++)
#pragma unroll
            for (int e = 0; e < 4; e++) acc[mt][nt][e] = 0.0f;

#define COMPUTE_CHUNK(st) do {                                                \
        uint32_t cb = sb + (uint32_t)(st) * STG_BYTES;                        \
        _Pragma("unroll")                                                     \
        for (int ks = 0; ks < 2; ks++) {                                      \
            uint32_t ah[4][4], al[4][4];                                      \
            int cch = ks * 2 + (lane >> 4);                                   \
            _Pragma("unroll")                                                 \
            for (int mt = 0; mt < 4; mt++) {                                  \
                int mr = wm * 64 + mt * 16 + (lane & 15);                     \
                uint32_t ad = cb + swz(mr, cch);                              \
                ldsm4(ah[mt][0], ah[mt][1], ah[mt][2], ah[mt][3], ad);        \
                ldsm4(al[mt][0], al[mt][1], al[mt][2], al[mt][3], ad + 8192); \
            }                                                                 \
            _Pragma("unroll")                                                 \
            for (int nt2 = 0; nt2 < 2; nt2++) {                               \
                int nr = wn * 32 + nt2 * 16 + (lane & 15);                    \
                uint32_t bd = cb + 16384 + swz(nr, cch);                      \
                uint32_t bh[4], bl[4];                                        \
                ldsm4(bh[0], bh[1], bh[2], bh[3], bd);                        \
                ldsm4(bl[0], bl[1], bl[2], bl[3], bd + 8192);                 \
                _Pragma("unroll")                                             \
                for (int mt = 0; mt < 4; mt++) {                              \
                    mma16816(acc[mt][nt2 * 2],     ah[mt], bh[0], bh[2]);     \
                    mma16816(acc[mt][nt2 * 2],     ah[mt], bl[0], bl[2]);     \
                    mma16816(acc[mt][nt2 * 2],     al[mt], bh[0], bh[2]);     \
                    mma16816(acc[mt][nt2 * 2 + 1], ah[mt], bh[1], bh[3]);     \
                    mma16816(acc[mt][nt2 * 2 + 1], ah[mt], bl[1], bl[3]);     \
                    mma16816(acc[mt][nt2 * 2 + 1], al[mt], bh[1], bh[3]);     \
                }                                                             \
            }                                                                 \
        }                                                                     \
    } while (0)

    // prologue: stages 0,1,2 <- chunks 0,1,2
    LOAD_CHUNK(0, 0);
    LOAD_CHUNK(1, 1);
    LOAD_CHUNK(2, 2);

    int st_c = 0;
#pragma unroll 1
    for (int kc = 0; kc < 6; kc++) {
        CP_WAIT(2);
        __syncthreads();
        COMPUTE_CHUNK(st_c);
        if (kc < 5) {
            __syncthreads();
            LOAD_CHUNK(kc + 3, st_c);
        }
        st_c = (st_c == 2) ? 0 : st_c + 1;
    }
    CP_WAIT(1); __syncthreads();
    COMPUTE_CHUNK(st_c);
    st_c = (st_c == 2) ? 0 : st_c + 1;
    CP_WAIT(0); __syncthreads();
    COMPUTE_CHUNK(st_c);

    // epilogue
#pragma unroll
    for (int mt = 0; mt < 4; mt++) {
        int r_lo = row0 + wm * 64 + mt * 16 + (lane >> 2);
        int r_hi = r_lo + 8;
#pragma unroll
        for (int nt = 0; nt < 4; nt++) {
            int cc = col0 + wn * 32 + nt * 8 + 2 * (lane & 3);
            if (r_lo < M)
                *(float2*)(&C[(size_t)r_lo * NC + cc]) = make_float2(acc[mt][nt][0], acc[mt][nt][1]);
            if (r_hi < M)
                *(float2*)(&C[(size_t)r_hi * NC + cc]) = make_float2(acc[mt][nt][2], acc[mt][nt][3]);
        }
    }
#undef LOAD_CHUNK
#undef COMPUTE_CHUNK
}

// ---------------- leaf elementwise (float4) ----------------------------------
__global__ void leaf_v4(const float* __restrict__ b_iou) {
    int gid = blockIdx.x * blockDim.x + threadIdx.x;
    const int total = BATCH * LV * 64;
    if (gid >= total) return;
    int d = (gid & 63) << 2;
    int rest = gid >> 6;
    int k = rest & (LV - 1);
    int bb = rest >> 14;
    size_t row = (size_t)bb * NNODE + NINT + k;

    float4 bi = *(const float4*)(b_iou + d);
    float4 bo = *(const float4*)(b_iou + 256 + d);
    float4 bu = *(const float4*)(b_iou + 512 + d);

    size_t xrow = row * NC;
    float4 i4 = add4(*(const float4*)(g_xproj + xrow + d), bi);
    float4 o4 = add4(*(const float4*)(g_xproj + xrow + 256 + d), bo);
    float4 u4 = add4(*(const float4*)(g_xproj + xrow + 512 + d), bu);
    float4 c4, h4;
    c4.x = sigm(i4.x) * tanhf(u4.x); h4.x = sigm(o4.x) * tanhf(c4.x);
    c4.y = sigm(i4.y) * tanhf(u4.y); h4.y = sigm(o4.y) * tanhf(c4.y);
    c4.z = sigm(i4.z) * tanhf(u4.z); h4.z = sigm(o4.z) * tanhf(c4.z);
    c4.w = sigm(i4.w) * tanhf(u4.w); h4.w = sigm(o4.w) * tanhf(c4.w);
    size_t hrow = row * 256 + d;
    *(float4*)(g_c + hrow) = c4;
    split_store4(g_hh + hrow, g_hl + hrow, h4);
}

// ---------------- internal-level combine (float4) ----------------------------
__global__ void combine_v4(const float* __restrict__ b_iou, const float* __restrict__ b_f, int n) {
    int gid = blockIdx.x * blockDim.x + threadIdx.x;
    const int total = BATCH * n * 64;
    if (gid >= total) return;
    int d = (gid & 63) << 2;
    int rest = gid >> 6;
    int k = rest % n;
    int bb = rest / n;
    int j = n - 1 + k;
    size_t row = (size_t)bb * NNODE + j;

    size_t r0 = ((size_t)bb * 2 * n + 2 * k) * NC;
    size_t r1 = r0 + NC;

    float4 bi = *(const float4*)(b_iou + d);
    float4 bo = *(const float4*)(b_iou + 256 + d);
    float4 bu = *(const float4*)(b_iou + 512 + d);
    float4 bf = *(const float4*)(b_f + d);

    size_t xrow = row * NC;
    float4 i4 = add4(add4(*(const float4*)(g_xproj + xrow + d),
                          add4(*(const float4*)(g_R + r0 + d), *(const float4*)(g_R + r1 + d))), bi);
    float4 o4 = add4(add4(*(const float4*)(g_xproj + xrow + 256 + d),
                          add4(*(const float4*)(g_R + r0 + 256 + d), *(const float4*)(g_R + r1 + 256 + d))), bo);
    float4 u4 = add4(add4(*(const float4*)(g_xproj + xrow + 512 + d),
                          add4(*(const float4*)(g_R + r0 + 512 + d), *(const float4*)(g_R + r1 + 512 + d))), bu);
    float4 fx = add4(*(const float4*)(g_xproj + xrow + 768 + d), bf);
    float4 f0 = *(const float4*)(g_R + r0 + 768 + d);
    float4 f1 = *(const float4*)(g_R + r1 + 768 + d);

    size_t crow = ((size_t)bb * NNODE + 2 * j + 1) * 256 + d;
    float4 c0 = *(const float4*)(g_c + crow);
    float4 c1 = *(const float4*)(g_c + crow + 256);

    float4 c4, h4;
    c4.x = sigm(i4.x) * tanhf(u4.x) + sigm(fx.x + f0.x) * c0.x + sigm(fx.x + f1.x) * c1.x;
    c4.y = sigm(i4.y) * tanhf(u4.y) + sigm(fx.y + f0.y) * c0.y + sigm(fx.y + f1.y) * c1.y;
    c4.z = sigm(i4.z) * tanhf(u4.z) + sigm(fx.z + f0.z) * c0.z + sigm(fx.z + f1.z) * c1.z;
    c4.w = sigm(i4.w) * tanhf(u4.w) + sigm(fx.w + f0.w) * c0.w + sigm(fx.w + f1.w) * c1.w;
    h4.x = sigm(o4.x) * tanhf(c4.x);
    h4.y = sigm(o4.y) * tanhf(c4.y);
    h4.z = sigm(o4.z) * tanhf(c4.z);
    h4.w = sigm(o4.w) * tanhf(c4.w);

    size_t hrow = row * 256 + d;
    *(float4*)(g_c + hrow) = c4;
    split_store4(g_hh + hrow, g_hl + hrow, h4);
}

// ---------------- output ----------------------------------------------------
__global__ void out_k(float* __restrict__ out) {
    int idx = blockIdx.x * blockDim.x + threadIdx.x;
    if (idx >= BATCH * 2 * DH) return;
    int bb = idx / (2 * DH);
    int d  = idx % (2 * DH);
    size_t row = (size_t)bb * NNODE;
    if (d < DH)
        out[idx] = __bfloat162float(g_hh[row * 256 + d]) + __bfloat162float(g_hl[row * 256 + d]);
    else
        out[idx] = g_c[row * 256 + (d - DH)];
}

// ---------------- launch ----------------------------------------------------
extern "C" void kernel_launch(void* const* d_in, const int* in_sizes, int n_in,
                              void* d_out, int out_size) {
    const float* x     = (const float*)d_in[0];
    const float* W_iou = (const float*)d_in[1];
    const float* b_iou = (const float*)d_in[2];
    const float* U_iou = (const float*)d_in[3];
    const float* W_f   = (const float*)d_in[4];
    const float* b_f   = (const float*)d_in[5];
    const float* U_f   = (const float*)d_in[6];
    float* out = (float*)d_out;

    cudaFuncSetAttribute(gemm_mma, cudaFuncAttributeMaxDynamicSharedMemorySize, SMEM_DYN);

    pack_weights<<<(NC * 256 + 255) / 256, 256>>>(W_iou, W_f, U_iou, U_f);
    {
        size_t n4 = (size_t)TOTAL_ROWS * 256 / 4;
        split_x<<<(unsigned)((n4 + 255) / 256), 256>>>(x);
    }

    // input projection for ALL nodes
    {
        dim3 grid(NC / TBN, (TOTAL_ROWS + TBM - 1) / TBM);
        gemm_mma<<<grid, 256, SMEM_DYN>>>(0, 0, 0, TOTAL_ROWS, TOTAL_ROWS, 0, 0);
    }

    // leaves
    leaf_v4<<<BATCH * LV * 64 / 256, 256>>>(b_iou);

    // levels, bottom-up (R8 structure, vectorized combine)
    for (int n = LVH; n >= 1; n >>= 1) {
        int rows = BATCH * 2 * n;
        dim3 grid(NC / TBN, (rows + TBM - 1) / TBM);
        gemm_mma<<<grid, 256, SMEM_DYN>>>(1, 1, 1, rows, 2 * n, 2 * n - 1, NNODE);
        int total = BATCH * n * 64;
        combine_v4<<<(total + 255) / 256, 256>>>(b_iou, b_f, n);
    }

    out_k<<<(BATCH * 2 * DH + 255) / 256, 256>>>(out);
}

// round 12
// speedup vs baseline: 1.2256x; 1.0364x over previous
#include <cuda_runtime.h>
#include <cuda_bf16.h>
#include <cuda_fp16.h>
#include <math.h>
#include <stdint.h>

// Problem constants
#define BATCH 8
#define LV    16384
#define LVH   8192
#define NNODE 32767
#define NINT  16383
#define DH    256
#define NC    1024
#define TOTAL_ROWS (BATCH * NNODE)   // 262136

// GEMM tiling (proven: 3 stages, 96KB -> 2 CTAs/SM)
#define TBM 128
#define TBN 128
#define NSTAGE 3
#define STG_BYTES 32768       // Ah(8K) Al(8K) Bh(8K) Bl(8K)
#define SMEM_DYN (NSTAGE * STG_BYTES)

// ---------------- scratch (device globals) ----------------------------------
__device__ __nv_bfloat16 g_Wh[NC * 256];
__device__ __nv_bfloat16 g_Wl[NC * 256];
__device__ __nv_bfloat16 g_Uh[NC * 256];
__device__ __nv_bfloat16 g_Ul[NC * 256];
__device__ __nv_bfloat16 g_xh[(size_t)TOTAL_ROWS * 256];
__device__ __nv_bfloat16 g_xl[(size_t)TOTAL_ROWS * 256];
__device__ __nv_bfloat16 g_hh[(size_t)TOTAL_ROWS * 256];
__device__ __nv_bfloat16 g_hl[(size_t)TOTAL_ROWS * 256];
__device__ __half g_xproj[(size_t)TOTAL_ROWS * NC];     // fp16 preactivations
__device__ float  g_c[(size_t)TOTAL_ROWS * 256];
__device__ __half g_R[(size_t)BATCH * LV * NC];         // fp16 recurrent proj

__device__ __forceinline__ float sigm(float x) { return 1.0f / (1.0f + expf(-x)); }

// ---------------- PTX helpers ------------------------------------------------
__device__ __forceinline__ uint32_t smem_u32(const void* p) {
    uint32_t a;
    asm("{ .reg .u64 t; cvta.to.shared.u64 t, %1; cvt.u32.u64 %0, t; }" : "=r"(a) : "l"(p));
    return a;
}
__device__ __forceinline__ void ldsm4(uint32_t& r0, uint32_t& r1, uint32_t& r2, uint32_t& r3, uint32_t addr) {
    asm volatile("ldmatrix.sync.aligned.m8n8.x4.shared.b16 {%0,%1,%2,%3},[%4];"
                 : "=r"(r0), "=r"(r1), "=r"(r2), "=r"(r3) : "r"(addr));
}
__device__ __forceinline__ void mma16816(float* c, const uint32_t* a, uint32_t b0, uint32_t b1) {
    asm volatile("mma.sync.aligned.m16n8k16.row.col.f32.bf16.bf16.f32 "
                 "{%0,%1,%2,%3},{%4,%5,%6,%7},{%8,%9},{%0,%1,%2,%3};"
                 : "+f"(c[0]), "+f"(c[1]), "+f"(c[2]), "+f"(c[3])
                 : "r"(a[0]), "r"(a[1]), "r"(a[2]), "r"(a[3]), "r"(b0), "r"(b1));
}
__device__ __forceinline__ void cp16(uint32_t dst, const void* src, int srcsz) {
    asm volatile("cp.async.cg.shared.global [%0], [%1], 16, %2;" :: "r"(dst), "l"(src), "r"(srcsz) : "memory");
}
#define CP_COMMIT() asm volatile("cp.async.commit_group;" ::: "memory")
#define CP_WAIT(n)  asm volatile("cp.async.wait_group %0;" :: "n"(n) : "memory")

__device__ __forceinline__ uint32_t swz(int r, int c) {
    return (uint32_t)(r * 64 + ((c ^ ((r >> 1) & 3)) << 4));
}
__device__ __forceinline__ void split_store4(__nv_bfloat16* hi, __nv_bfloat16* lo, float4 v) {
    __nv_bfloat16 a = __float2bfloat16_rn(v.x), b = __float2bfloat16_rn(v.y),
                  c = __float2bfloat16_rn(v.z), e = __float2bfloat16_rn(v.w);
    *(__nv_bfloat162*)(hi)     = __nv_bfloat162(a, b);
    *(__nv_bfloat162*)(hi + 2) = __nv_bfloat162(c, e);
    *(__nv_bfloat162*)(lo)     = __nv_bfloat162(__float2bfloat16_rn(v.x - __bfloat162float(a)),
                                                __float2bfloat16_rn(v.y - __bfloat162float(b)));
    *(__nv_bfloat162*)(lo + 2) = __nv_bfloat162(__float2bfloat16_rn(v.z - __bfloat162float(c)),
                                                __float2bfloat16_rn(v.w - __bfloat162float(e)));
}
__device__ __forceinline__ float4 add4(float4 a, float4 b) {
    return make_float4(a.x + b.x, a.y + b.y, a.z + b.z, a.w + b.w);
}
// load 4 halves -> float4
__device__ __forceinline__ float4 ld4h(const __half* p) {
    __half2 a = *(const __half2*)p;
    __half2 b = *(const __half2*)(p + 2);
    return make_float4(__low2float(a), __high2float(a), __low2float(b), __high2float(b));
}

// ---------------- weight packing ---------------------------------------------
__global__ void pack_weights(const float* __restrict__ W_iou, const float* __restrict__ W_f,
                             const float* __restrict__ U_iou, const float* __restrict__ U_f) {
    int idx = blockIdx.x * blockDim.x + threadIdx.x;
    if (idx >= NC * 256) return;
    int j = idx / 256, k = idx % 256;
    float wv = (j < 768) ? W_iou[k * 768 + j] : W_f[k * 256 + (j - 768)];
    float uv = (j < 768) ? U_iou[k * 768 + j] : U_f[k * 256 + (j - 768)];
    __nv_bfloat16 wh = __float2bfloat16_rn(wv);
    g_Wh[idx] = wh;
    g_Wl[idx] = __float2bfloat16_rn(wv - __bfloat162float(wh));
    __nv_bfloat16 uh = __float2bfloat16_rn(uv);
    g_Uh[idx] = uh;
    g_Ul[idx] = __float2bfloat16_rn(uv - __bfloat162float(uh));
}

// ---------------- x hi/lo split ----------------------------------------------
__global__ void split_x(const float* __restrict__ x) {
    size_t i = (size_t)blockIdx.x * blockDim.x + threadIdx.x;
    const size_t n4 = (size_t)TOTAL_ROWS * 256 / 4;
    if (i >= n4) return;
    float4 v = ((const float4*)x)[i];
    split_store4(g_xh + 4 * i, g_xl + 4 * i, v);
}

// ---------------- mma.sync GEMM: C[M x 1024] = A[M x 256] @ W ----------------
// CTA tile 128x128x32, warp tile 64x32 (8 warps 2x4), 3-term bf16 split.
// 3 stages, two barriers per chunk, 96KB smem (2 CTAs/SM). fp16 C output.
__global__ __launch_bounds__(256, 2)
void gemm_mma(int asel, int wsel, int csel, int M, int rpb, int row_off, int node_stride)
{
    extern __shared__ char smem[];
    const uint32_t sb = smem_u32(smem);
    const int tid = threadIdx.x, wid = tid >> 5, lane = tid & 31;
    const int wm = wid >> 2, wn = wid & 3;
    const int row0 = blockIdx.y * TBM;
    const int col0 = blockIdx.x * TBN;

    const __nv_bfloat16* Ahg = asel ? g_hh : g_xh;
    const __nv_bfloat16* Alg = asel ? g_hl : g_xl;
    const __nv_bfloat16* Bhg = wsel ? g_Uh : g_Wh;
    const __nv_bfloat16* Blg = wsel ? g_Ul : g_Wl;
    __half* C = csel ? g_R : g_xproj;

    const int lr = tid >> 1;
    const int c2 = (tid & 1) * 2;
    size_t aoff; int asz;
    {
        int m = row0 + lr;
        if (m < M) {
            int bb = m / rpb, loc = m - bb * rpb;
            aoff = ((size_t)bb * node_stride + (size_t)(row_off + loc)) * 256;
            asz = 16;
        } else { aoff = 0; asz = 0; }
    }
    const size_t boff = (size_t)(col0 + lr) * 256;
    const uint32_t s0 = swz(lr, c2), s1 = swz(lr, c2 + 1);

#define LOAD_CHUNK(kc, st) do {                                               \
        uint32_t bs = sb + (uint32_t)(st) * STG_BYTES;                        \
        int kg = (kc) * 32;                                                   \
        cp16(bs + s0,          Ahg + aoff + kg + c2 * 8,       asz);          \
        cp16(bs + s1,          Ahg + aoff + kg + c2 * 8 + 8,   asz);          \
        cp16(bs + 8192 + s0,   Alg + aoff + kg + c2 * 8,       asz);          \
        cp16(bs + 8192 + s1,   Alg + aoff + kg + c2 * 8 + 8,   asz);          \
        cp16(bs + 16384 + s0,  Bhg + boff + kg + c2 * 8,       16);           \
        cp16(bs + 16384 + s1,  Bhg + boff + kg + c2 * 8 + 8,   16);           \
        cp16(bs + 24576 + s0,  Blg + boff + kg + c2 * 8,       16);           \
        cp16(bs + 24576 + s1,  Blg + boff + kg + c2 * 8 + 8,   16);           \
        CP_COMMIT();                                                          \
    } while (0)

    float acc[4][4][4];
#pragma unroll
    for (int mt = 0; mt < 4; mt++)
#pragma unroll
        for (int nt = 0; nt < 4; nt++)
#pragma unroll
            for (int e = 0; e < 4; e++) acc[mt][nt][e] = 0.0f;

#define COMPUTE_CHUNK(st) do {                                                \
        uint32_t cb = sb + (uint32_t)(st) * STG_BYTES;                        \
        _Pragma("unroll")                                                     \
        for (int ks = 0; ks < 2; ks++) {                                      \
            uint32_t ah[4][4], al[4][4];                                      \
            int cch = ks * 2 + (lane >> 4);                                   \
            _Pragma("unroll")                                                 \
            for (int mt = 0; mt < 4; mt++) {                                  \
                int mr = wm * 64 + mt * 16 + (lane & 15);                     \
                uint32_t ad = cb + swz(mr, cch);                              \
                ldsm4(ah[mt][0], ah[mt][1], ah[mt][2], ah[mt][3], ad);        \
                ldsm4(al[mt][0], al[mt][1], al[mt][2], al[mt][3], ad + 8192); \
            }                                                                 \
            _Pragma("unroll")                                                 \
            for (int nt2 = 0; nt2 < 2; nt2++) {                               \
                int nr = wn * 32 + nt2 * 16 + (lane & 15);                    \
                uint32_t bd = cb + 16384 + swz(nr, cch);                      \
                uint32_t bh[4], bl[4];                                        \
                ldsm4(bh[0], bh[1], bh[2], bh[3], bd);                        \
                ldsm4(bl[0], bl[1], bl[2], bl[3], bd + 8192);                 \
                _Pragma("unroll")                                             \
                for (int mt = 0; mt < 4; mt++) {                              \
                    mma16816(acc[mt][nt2 * 2],     ah[mt], bh[0], bh[2]);     \
                    mma16816(acc[mt][nt2 * 2],     ah[mt], bl[0], bl[2]);     \
                    mma16816(acc[mt][nt2 * 2],     al[mt], bh[0], bh[2]);     \
                    mma16816(acc[mt][nt2 * 2 + 1], ah[mt], bh[1], bh[3]);     \
                    mma16816(acc[mt][nt2 * 2 + 1], ah[mt], bl[1], bl[3]);     \
                    mma16816(acc[mt][nt2 * 2 + 1], al[mt], bh[1], bh[3]);     \
                }                                                             \
            }                                                                 \
        }                                                                     \
    } while (0)

    // prologue: stages 0,1,2 <- chunks 0,1,2
    LOAD_CHUNK(0, 0);
    LOAD_CHUNK(1, 1);
    LOAD_CHUNK(2, 2);

    int st_c = 0;
#pragma unroll 1
    for (int kc = 0; kc < 6; kc++) {
        CP_WAIT(2);
        __syncthreads();
        COMPUTE_CHUNK(st_c);
        if (kc < 5) {
            __syncthreads();
            LOAD_CHUNK(kc + 3, st_c);
        }
        st_c = (st_c == 2) ? 0 : st_c + 1;
    }
    CP_WAIT(1); __syncthreads();
    COMPUTE_CHUNK(st_c);
    st_c = (st_c == 2) ? 0 : st_c + 1;
    CP_WAIT(0); __syncthreads();
    COMPUTE_CHUNK(st_c);

    // epilogue (fp16 stores)
#pragma unroll
    for (int mt = 0; mt < 4; mt++) {
        int r_lo = row0 + wm * 64 + mt * 16 + (lane >> 2);
        int r_hi = r_lo + 8;
#pragma unroll
        for (int nt = 0; nt < 4; nt++) {
            int cc = col0 + wn * 32 + nt * 8 + 2 * (lane & 3);
            if (r_lo < M)
                *(__half2*)(&C[(size_t)r_lo * NC + cc]) = __floats2half2_rn(acc[mt][nt][0], acc[mt][nt][1]);
            if (r_hi < M)
                *(__half2*)(&C[(size_t)r_hi * NC + cc]) = __floats2half2_rn(acc[mt][nt][2], acc[mt][nt][3]);
        }
    }
#undef LOAD_CHUNK
#undef COMPUTE_CHUNK
}

// ---------------- leaf elementwise (float4, fp16 xproj) ----------------------
__global__ void leaf_v4(const float* __restrict__ b_iou) {
    int gid = blockIdx.x * blockDim.x + threadIdx.x;
    const int total = BATCH * LV * 64;
    if (gid >= total) return;
    int d = (gid & 63) << 2;
    int rest = gid >> 6;
    int k = rest & (LV - 1);
    int bb = rest >> 14;
    size_t row = (size_t)bb * NNODE + NINT + k;

    float4 bi = *(const float4*)(b_iou + d);
    float4 bo = *(const float4*)(b_iou + 256 + d);
    float4 bu = *(const float4*)(b_iou + 512 + d);

    const __half* xp = g_xproj + row * NC;
    float4 i4 = add4(ld4h(xp + d), bi);
    float4 o4 = add4(ld4h(xp + 256 + d), bo);
    float4 u4 = add4(ld4h(xp + 512 + d), bu);
    float4 c4, h4;
    c4.x = sigm(i4.x) * tanhf(u4.x); h4.x = sigm(o4.x) * tanhf(c4.x);
    c4.y = sigm(i4.y) * tanhf(u4.y); h4.y = sigm(o4.y) * tanhf(c4.y);
    c4.z = sigm(i4.z) * tanhf(u4.z); h4.z = sigm(o4.z) * tanhf(c4.z);
    c4.w = sigm(i4.w) * tanhf(u4.w); h4.w = sigm(o4.w) * tanhf(c4.w);
    size_t hrow = row * 256 + d;
    *(float4*)(g_c + hrow) = c4;
    split_store4(g_hh + hrow, g_hl + hrow, h4);
}

// ---------------- internal-level combine (float4, fp16 xproj/R) --------------
__global__ void combine_v4(const float* __restrict__ b_iou, const float* __restrict__ b_f, int n) {
    int gid = blockIdx.x * blockDim.x + threadIdx.x;
    const int total = BATCH * n * 64;
    if (gid >= total) return;
    int d = (gid & 63) << 2;
    int rest = gid >> 6;
    int k = rest % n;
    int bb = rest / n;
    int j = n - 1 + k;
    size_t row = (size_t)bb * NNODE + j;

    const __half* R0 = g_R + ((size_t)bb * 2 * n + 2 * k) * NC;
    const __half* R1 = R0 + NC;

    float4 bi = *(const float4*)(b_iou + d);
    float4 bo = *(const float4*)(b_iou + 256 + d);
    float4 bu = *(const float4*)(b_iou + 512 + d);
    float4 bf = *(const float4*)(b_f + d);

    const __half* xp = g_xproj + row * NC;
    float4 i4 = add4(add4(ld4h(xp + d),       add4(ld4h(R0 + d),       ld4h(R1 + d))),       bi);
    float4 o4 = add4(add4(ld4h(xp + 256 + d), add4(ld4h(R0 + 256 + d), ld4h(R1 + 256 + d))), bo);
    float4 u4 = add4(add4(ld4h(xp + 512 + d), add4(ld4h(R0 + 512 + d), ld4h(R1 + 512 + d))), bu);
    float4 fx = add4(ld4h(xp + 768 + d), bf);
    float4 f0 = ld4h(R0 + 768 + d);
    float4 f1 = ld4h(R1 + 768 + d);

    size_t crow = ((size_t)bb * NNODE + 2 * j + 1) * 256 + d;
    float4 c0 = *(const float4*)(g_c + crow);
    float4 c1 = *(const float4*)(g_c + crow + 256);

    float4 c4, h4;
    c4.x = sigm(i4.x) * tanhf(u4.x) + sigm(fx.x + f0.x) * c0.x + sigm(fx.x + f1.x) * c1.x;
    c4.y = sigm(i4.y) * tanhf(u4.y) + sigm(fx.y + f0.y) * c0.y + sigm(fx.y + f1.y) * c1.y;
    c4.z = sigm(i4.z) * tanhf(u4.z) + sigm(fx.z + f0.z) * c0.z + sigm(fx.z + f1.z) * c1.z;
    c4.w = sigm(i4.w) * tanhf(u4.w) + sigm(fx.w + f0.w) * c0.w + sigm(fx.w + f1.w) * c1.w;
    h4.x = sigm(o4.x) * tanhf(c4.x);
    h4.y = sigm(o4.y) * tanhf(c4.y);
    h4.z = sigm(o4.z) * tanhf(c4.z);
    h4.w = sigm(o4.w) * tanhf(c4.w);

    size_t hrow = row * 256 + d;
    *(float4*)(g_c + hrow) = c4;
    split_store4(g_hh + hrow, g_hl + hrow, h4);
}

// ---------------- output ----------------------------------------------------
__global__ void out_k(float* __restrict__ out) {
    int idx = blockIdx.x * blockDim.x + threadIdx.x;
    if (idx >= BATCH * 2 * DH) return;
    int bb = idx / (2 * DH);
    int d  = idx % (2 * DH);
    size_t row = (size_t)bb * NNODE;
    if (d < DH)
        out[idx] = __bfloat162float(g_hh[row * 256 + d]) + __bfloat162float(g_hl[row * 256 + d]);
    else
        out[idx] = g_c[row * 256 + (d - DH)];
}

// ---------------- launch ----------------------------------------------------
extern "C" void kernel_launch(void* const* d_in, const int* in_sizes, int n_in,
                              void* d_out, int out_size) {
    const float* x     = (const float*)d_in[0];
    const float* W_iou = (const float*)d_in[1];
    const float* b_iou = (const float*)d_in[2];
    const float* U_iou = (const float*)d_in[3];
    const float* W_f   = (const float*)d_in[4];
    const float* b_f   = (const float*)d_in[5];
    const float* U_f   = (const float*)d_in[6];
    float* out = (float*)d_out;

    cudaFuncSetAttribute(gemm_mma, cudaFuncAttributeMaxDynamicSharedMemorySize, SMEM_DYN);

    pack_weights<<<(NC * 256 + 255) / 256, 256>>>(W_iou, W_f, U_iou, U_f);
    {
        size_t n4 = (size_t)TOTAL_ROWS * 256 / 4;
        split_x<<<(unsigned)((n4 + 255) / 256), 256>>>(x);
    }

    // input projection for ALL nodes
    {
        dim3 grid(NC / TBN, (TOTAL_ROWS + TBM - 1) / TBM);
        gemm_mma<<<grid, 256, SMEM_DYN>>>(0, 0, 0, TOTAL_ROWS, TOTAL_ROWS, 0, 0);
    }

    // leaves
    leaf_v4<<<BATCH * LV * 64 / 256, 256>>>(b_iou);

    // levels, bottom-up
    for (int n = LVH; n >= 1; n >>= 1) {
        int rows = BATCH * 2 * n;
        dim3 grid(NC / TBN, (rows + TBM - 1) / TBM);
        gemm_mma<<<grid, 256, SMEM_DYN>>>(1, 1, 1, rows, 2 * n, 2 * n - 1, NNODE);
        int total = BATCH * n * 64;
        combine_v4<<<(total + 255) / 256, 256>>>(b_iou, b_f, n);
    }

    out_k<<<(BATCH * 2 * DH + 255) / 256, 256>>>(out);
}

// round 14
// speedup vs baseline: 1.2290x; 1.0027x over previous
#include <cuda_runtime.h>
#include <cuda_bf16.h>
#include <cuda_fp16.h>
#include <math.h>
#include <stdint.h>

// Problem constants
#define BATCH 8
#define LV    16384
#define LVH   8192
#define NNODE 32767
#define NINT  16383
#define DH    256
#define NC    1024
#define TOTAL_ROWS (BATCH * NNODE)   // 262136

// GEMM tiling (proven: 3 stages, 96KB -> 2 CTAs/SM)
#define TBM 128
#define TBN 128
#define NSTAGE 3
#define STG_BYTES 32768       // Ah(8K) Al(8K) Bh(8K) Bl(8K)
#define SMEM_DYN (NSTAGE * STG_BYTES)

// ---------------- scratch (device globals) ----------------------------------
__device__ __nv_bfloat16 g_Wh[NC * 256];
__device__ __nv_bfloat16 g_Wl[NC * 256];
__device__ __nv_bfloat16 g_Uh[NC * 256];
__device__ __nv_bfloat16 g_Ul[NC * 256];
__device__ __nv_bfloat16 g_xh[(size_t)TOTAL_ROWS * 256];
__device__ __nv_bfloat16 g_xl[(size_t)TOTAL_ROWS * 256];
__device__ __nv_bfloat16 g_hh[(size_t)TOTAL_ROWS * 256];
__device__ __nv_bfloat16 g_hl[(size_t)TOTAL_ROWS * 256];
__device__ __nv_bfloat16 g_sh[(size_t)BATCH * LVH * 256];   // sibling h-sum hi
__device__ __nv_bfloat16 g_sl[(size_t)BATCH * LVH * 256];   // sibling h-sum lo
__device__ __half g_xproj[(size_t)TOTAL_ROWS * NC];         // fp16 preactivations
__device__ float  g_c[(size_t)TOTAL_ROWS * 256];
__device__ __half g_Riou[(size_t)BATCH * LVH * 768];        // hsum @ U_iou
__device__ __half g_Rf[(size_t)BATCH * LV * 256];           // h_child @ U_f

__device__ __forceinline__ float sigm(float x) { return 1.0f / (1.0f + expf(-x)); }

// ---------------- PTX helpers ------------------------------------------------
__device__ __forceinline__ uint32_t smem_u32(const void* p) {
    uint32_t a;
    asm("{ .reg .u64 t; cvta.to.shared.u64 t, %1; cvt.u32.u64 %0, t; }" : "=r"(a) : "l"(p));
    return a;
}
__device__ __forceinline__ void ldsm4(uint32_t& r0, uint32_t& r1, uint32_t& r2, uint32_t& r3, uint32_t addr) {
    asm volatile("ldmatrix.sync.aligned.m8n8.x4.shared.b16 {%0,%1,%2,%3},[%4];"
                 : "=r"(r0), "=r"(r1), "=r"(r2), "=r"(r3) : "r"(addr));
}
__device__ __forceinline__ void mma16816(float* c, const uint32_t* a, uint32_t b0, uint32_t b1) {
    asm volatile("mma.sync.aligned.m16n8k16.row.col.f32.bf16.bf16.f32 "
                 "{%0,%1,%2,%3},{%4,%5,%6,%7},{%8,%9},{%0,%1,%2,%3};"
                 : "+f"(c[0]), "+f"(c[1]), "+f"(c[2]), "+f"(c[3])
                 : "r"(a[0]), "r"(a[1]), "r"(a[2]), "r"(a[3]), "r"(b0), "r"(b1));
}
__device__ __forceinline__ void cp16(uint32_t dst, const void* src, int srcsz) {
    asm volatile("cp.async.cg.shared.global [%0], [%1], 16, %2;" :: "r"(dst), "l"(src), "r"(srcsz) : "memory");
}
#define CP_COMMIT() asm volatile("cp.async.commit_group;" ::: "memory")
#define CP_WAIT(n)  asm volatile("cp.async.wait_group %0;" :: "n"(n) : "memory")

__device__ __forceinline__ uint32_t swz(int r, int c) {
    return (uint32_t)(r * 64 + ((c ^ ((r >> 1) & 3)) << 4));
}
__device__ __forceinline__ void split_store4(__nv_bfloat16* hi, __nv_bfloat16* lo, float4 v) {
    __nv_bfloat16 a = __float2bfloat16_rn(v.x), b = __float2bfloat16_rn(v.y),
                  c = __float2bfloat16_rn(v.z), e = __float2bfloat16_rn(v.w);
    *(__nv_bfloat162*)(hi)     = __nv_bfloat162(a, b);
    *(__nv_bfloat162*)(hi + 2) = __nv_bfloat162(c, e);
    *(__nv_bfloat162*)(lo)     = __nv_bfloat162(__float2bfloat16_rn(v.x - __bfloat162float(a)),
                                                __float2bfloat16_rn(v.y - __bfloat162float(b)));
    *(__nv_bfloat162*)(lo + 2) = __nv_bfloat162(__float2bfloat16_rn(v.z - __bfloat162float(c)),
                                                __float2bfloat16_rn(v.w - __bfloat162float(e)));
}
__device__ __forceinline__ float4 add4(float4 a, float4 b) {
    return make_float4(a.x + b.x, a.y + b.y, a.z + b.z, a.w + b.w);
}
__device__ __forceinline__ float4 ld4h(const __half* p) {
    __half2 a = *(const __half2*)p;
    __half2 b = *(const __half2*)(p + 2);
    return make_float4(__low2float(a), __high2float(a), __low2float(b), __high2float(b));
}

// ---------------- weight packing ---------------------------------------------
__global__ void pack_weights(const float* __restrict__ W_iou, const float* __restrict__ W_f,
                             const float* __restrict__ U_iou, const float* __restrict__ U_f) {
    int idx = blockIdx.x * blockDim.x + threadIdx.x;
    if (idx >= NC * 256) return;
    int j = idx / 256, k = idx % 256;
    float wv = (j < 768) ? W_iou[k * 768 + j] : W_f[k * 256 + (j - 768)];
    float uv = (j < 768) ? U_iou[k * 768 + j] : U_f[k * 256 + (j - 768)];
    __nv_bfloat16 wh = __float2bfloat16_rn(wv);
    g_Wh[idx] = wh;
    g_Wl[idx] = __float2bfloat16_rn(wv - __bfloat162float(wh));
    __nv_bfloat16 uh = __float2bfloat16_rn(uv);
    g_Uh[idx] = uh;
    g_Ul[idx] = __float2bfloat16_rn(uv - __bfloat162float(uh));
}

// ---------------- x hi/lo split ----------------------------------------------
__global__ void split_x(const float* __restrict__ x) {
    size_t i = (size_t)blockIdx.x * blockDim.x + threadIdx.x;
    const size_t n4 = (size_t)TOTAL_ROWS * 256 / 4;
    if (i >= n4) return;
    float4 v = ((const float4*)x)[i];
    split_store4(g_xh + 4 * i, g_xl + 4 * i, v);
}

// ---------------- mma.sync GEMM (3-term bf16 split) --------------------------
// C[crow, ccol] = A[M x 256] @ B[:, bcol..]; tile 128x128x32, 3-stage pipeline.
// A row m -> ((m/rpb)*node_stride + row_off + (m%rpb)) * 256
// C row m -> (m/rpb)*cns + (m%rpb); ldc/ccol parameterized.
__global__ __launch_bounds__(256, 2)
void gemm_mma(int asel, int wsel, int csel, int M, int rpb, int row_off, int node_stride,
              int bcol, int ccol, int ldc, int cns)
{
    extern __shared__ char smem[];
    const uint32_t sb = smem_u32(smem);
    const int tid = threadIdx.x, wid = tid >> 5, lane = tid & 31;
    const int wm = wid >> 2, wn = wid & 3;
    const int row0 = blockIdx.y * TBM;
    const int col0 = bcol + blockIdx.x * TBN;
    const int ccol0 = ccol + blockIdx.x * TBN;

    const __nv_bfloat16* Ahg = (asel == 0) ? g_xh : (asel == 1) ? g_hh : g_sh;
    const __nv_bfloat16* Alg = (asel == 0) ? g_xl : (asel == 1) ? g_hl : g_sl;
    const __nv_bfloat16* Bhg = wsel ? g_Uh : g_Wh;
    const __nv_bfloat16* Blg = wsel ? g_Ul : g_Wl;
    __half* C = (csel == 0) ? g_xproj : (csel == 1) ? g_Riou : g_Rf;

    const int lr = tid >> 1;
    const int c2 = (tid & 1) * 2;
    size_t aoff; int asz;
    {
        int m = row0 + lr;
        if (m < M) {
            int bb = m / rpb, loc = m - bb * rpb;
            aoff = ((size_t)bb * node_stride + (size_t)(row_off + loc)) * 256;
            asz = 16;
        } else { aoff = 0; asz = 0; }
    }
    const size_t boff = (size_t)(col0 + lr) * 256;
    const uint32_t s0 = swz(lr, c2), s1 = swz(lr, c2 + 1);

#define LOAD_CHUNK(kc, st) do {                                               \
        uint32_t bs = sb + (uint32_t)(st) * STG_BYTES;                        \
        int kg = (kc) * 32;                                                   \
        cp16(bs + s0,          Ahg + aoff + kg + c2 * 8,       asz);          \
        cp16(bs + s1,          Ahg + aoff + kg + c2 * 8 + 8,   asz);          \
        cp16(bs + 8192 + s0,   Alg + aoff + kg + c2 * 8,       asz);          \
        cp16(bs + 8192 + s1,   Alg + aoff + kg + c2 * 8 + 8,   asz);          \
        cp16(bs + 16384 + s0,  Bhg + boff + kg + c2 * 8,       16);           \
        cp16(bs + 16384 + s1,  Bhg + boff + kg + c2 * 8 + 8,   16);           \
        cp16(bs + 24576 + s0,  Blg + boff + kg + c2 * 8,       16);           \
        cp16(bs + 24576 + s1,  Blg + boff + kg + c2 * 8 + 8,   16);           \
        CP_COMMIT();                                                          \
    } while (0)

    float acc[4][4][4];
#pragma unroll
    for (int mt = 0; mt < 4; mt++)
#pragma unroll
        for (int nt = 0; nt < 4; nt++)
#pragma unroll
            for (int e = 0; e < 4; e++) acc[mt][nt][e] = 0.0f;

#define COMPUTE_CHUNK(st) do {                                                \
        uint32_t cb = sb + (uint32_t)(st) * STG_BYTES;                        \
        _Pragma("unroll")                                                     \
        for (int ks = 0; ks < 2; ks++) {                                      \
            uint32_t ah[4][4], al[4][4];                                      \
            int cch = ks * 2 + (lane >> 4);                                   \
            _Pragma("unroll")                                                 \
            for (int mt = 0; mt < 4; mt++) {                                  \
                int mr = wm * 64 + mt * 16 + (lane & 15);                     \
                uint32_t ad = cb + swz(mr, cch);                              \
                ldsm4(ah[mt][0], ah[mt][1], ah[mt][2], ah[mt][3], ad);        \
                ldsm4(al[mt][0], al[mt][1], al[mt][2], al[mt][3], ad + 8192); \
            }                                                                 \
            _Pragma("unroll")                                                 \
            for (int nt2 = 0; nt2 < 2; nt2++) {                               \
                int nr = wn * 32 + nt2 * 16 + (lane & 15);                    \
                uint32_t bd = cb + 16384 + swz(nr, cch);                      \
                uint32_t bh[4], bl[4];                                        \
                ldsm4(bh[0], bh[1], bh[2], bh[3], bd);                        \
                ldsm4(bl[0], bl[1], bl[2], bl[3], bd + 8192);                 \
                _Pragma("unroll")                                             \
                for (int mt = 0; mt < 4; mt++) {                              \
                    mma16816(acc[mt][nt2 * 2],     ah[mt], bh[0], bh[2]);     \
                    mma16816(acc[mt][nt2 * 2],     ah[mt], bl[0], bl[2]);     \
                    mma16816(acc[mt][nt2 * 2],     al[mt], bh[0], bh[2]);     \
                    mma16816(acc[mt][nt2 * 2 + 1], ah[mt], bh[1], bh[3]);     \
                    mma16816(acc[mt][nt2 * 2 + 1], ah[mt], bl[1], bl[3]);     \
                    mma16816(acc[mt][nt2 * 2 + 1], al[mt], bh[1], bh[3]);     \
                }                                                             \
            }                                                                 \
        }                                                                     \
    } while (0)

    LOAD_CHUNK(0, 0);
    LOAD_CHUNK(1, 1);
    LOAD_CHUNK(2, 2);

    int st_c = 0;
#pragma unroll 1
    for (int kc = 0; kc < 6; kc++) {
        CP_WAIT(2);
        __syncthreads();
        COMPUTE_CHUNK(st_c);
        if (kc < 5) {
            __syncthreads();
            LOAD_CHUNK(kc + 3, st_c);
        }
        st_c = (st_c == 2) ? 0 : st_c + 1;
    }
    CP_WAIT(1); __syncthreads();
    COMPUTE_CHUNK(st_c);
    st_c = (st_c == 2) ? 0 : st_c + 1;
    CP_WAIT(0); __syncthreads();
    COMPUTE_CHUNK(st_c);

    // epilogue (fp16 stores, remapped C rows)
#pragma unroll
    for (int mt = 0; mt < 4; mt++) {
        int r_lo = row0 + wm * 64 + mt * 16 + (lane >> 2);
        int r_hi = r_lo + 8;
#pragma unroll
        for (int nt = 0; nt < 4; nt++) {
            int cc = ccol0 + wn * 32 + nt * 8 + 2 * (lane & 3);
            if (r_lo < M) {
                int bb = r_lo / rpb, loc = r_lo - bb * rpb;
                *(__half2*)(&C[((size_t)bb * cns + loc) * ldc + cc]) =
                    __floats2half2_rn(acc[mt][nt][0], acc[mt][nt][1]);
            }
            if (r_hi < M) {
                int bb = r_hi / rpb, loc = r_hi - bb * rpb;
                *(__half2*)(&C[((size_t)bb * cns + loc) * ldc + cc]) =
                    __floats2half2_rn(acc[mt][nt][2], acc[mt][nt][3]);
            }
        }
    }
#undef LOAD_CHUNK
#undef COMPUTE_CHUNK
}

// ---------------- leaf pairs: gates + h-sum for n=8192 parents ---------------
__global__ void leaf_pair(const float* __restrict__ b_iou) {
    int gid = blockIdx.x * blockDim.x + threadIdx.x;
    const int total = BATCH * LVH * 64;
    if (gid >= total) return;
    int d = (gid & 63) << 2;
    int rest = gid >> 6;
    int t = rest & (LVH - 1);
    int bb = rest >> 13;

    float4 bi = *(const float4*)(b_iou + d);
    float4 bo = *(const float4*)(b_iou + 256 + d);
    float4 bu = *(const float4*)(b_iou + 512 + d);

    float4 hs = make_float4(0.f, 0.f, 0.f, 0.f);
#pragma unroll
    for (int s = 0; s < 2; s++) {
        size_t row = (size_t)bb * NNODE + NINT + 2 * t + s;
        const __half* xp = g_xproj + row * NC;
        float4 i4 = add4(ld4h(xp + d), bi);
        float4 o4 = add4(ld4h(xp + 256 + d), bo);
        float4 u4 = add4(ld4h(xp + 512 + d), bu);
        float4 c4, h4;
        c4.x = sigm(i4.x) * tanhf(u4.x); h4.x = sigm(o4.x) * tanhf(c4.x);
        c4.y = sigm(i4.y) * tanhf(u4.y); h4.y = sigm(o4.y) * tanhf(c4.y);
        c4.z = sigm(i4.z) * tanhf(u4.z); h4.z = sigm(o4.z) * tanhf(c4.z);
        c4.w = sigm(i4.w) * tanhf(u4.w); h4.w = sigm(o4.w) * tanhf(c4.w);
        size_t hrow = row * 256 + d;
        *(float4*)(g_c + hrow) = c4;
        split_store4(g_hh + hrow, g_hl + hrow, h4);
        hs = add4(hs, h4);
    }
    size_t srow = ((size_t)bb * LVH + t) * 256 + d;
    split_store4(g_sh + srow, g_sl + srow, hs);
}

// ---------------- combine pairs: level n parents + next h-sum ----------------
__global__ void combine_pair(const float* __restrict__ b_iou, const float* __restrict__ b_f, int n) {
    int gid = blockIdx.x * blockDim.x + threadIdx.x;
    const int half = (n >= 2) ? (n >> 1) : 1;
    const int npair = (n >= 2) ? 2 : 1;
    const int total = BATCH * half * 64;
    if (gid >= total) return;
    int d = (gid & 63) << 2;
    int rest = gid >> 6;
    int t = rest % half;
    int bb = rest / half;

    float4 bi = *(const float4*)(b_iou + d);
    float4 bo = *(const float4*)(b_iou + 256 + d);
    float4 bu = *(const float4*)(b_iou + 512 + d);
    float4 bf = *(const float4*)(b_f + d);

    float4 hs = make_float4(0.f, 0.f, 0.f, 0.f);
#pragma unroll
    for (int s = 0; s < 2; s++) {
        if (s >= npair) break;
        int k = npair * t + s;
        int j = n - 1 + k;
        size_t row = (size_t)bb * NNODE + j;
        const __half* xp = g_xproj + row * NC;
        const __half* Ri = g_Riou + ((size_t)bb * n + k) * 768;
        const __half* Rf0 = g_Rf + ((size_t)bb * 2 * n + 2 * k) * 256;
        const __half* Rf1 = Rf0 + 256;

        float4 i4 = add4(add4(ld4h(xp + d),       ld4h(Ri + d)),       bi);
        float4 o4 = add4(add4(ld4h(xp + 256 + d), ld4h(Ri + 256 + d)), bo);
        float4 u4 = add4(add4(ld4h(xp + 512 + d), ld4h(Ri + 512 + d)), bu);
        float4 fx = add4(ld4h(xp + 768 + d), bf);
        float4 f0 = ld4h(Rf0 + d);
        float4 f1 = ld4h(Rf1 + d);

        size_t crow = ((size_t)bb * NNODE + 2 * j + 1) * 256 + d;
        float4 c0 = *(const float4*)(g_c + crow);
        float4 c1 = *(const float4*)(g_c + crow + 256);

        float4 c4, h4;
        c4.x = sigm(i4.x) * tanhf(u4.x) + sigm(fx.x + f0.x) * c0.x + sigm(fx.x + f1.x) * c1.x;
        c4.y = sigm(i4.y) * tanhf(u4.y) + sigm(fx.y + f0.y) * c0.y + sigm(fx.y + f1.y) * c1.y;
        c4.z = sigm(i4.z) * tanhf(u4.z) + sigm(fx.z + f0.z) * c0.z + sigm(fx.z + f1.z) * c1.z;
        c4.w = sigm(i4.w) * tanhf(u4.w) + sigm(fx.w + f0.w) * c0.w + sigm(fx.w + f1.w) * c1.w;
        h4.x = sigm(o4.x) * tanhf(c4.x);
        h4.y = sigm(o4.y) * tanhf(c4.y);
        h4.z = sigm(o4.z) * tanhf(c4.z);
        h4.w = sigm(o4.w) * tanhf(c4.w);

        size_t hrow = row * 256 + d;
        *(float4*)(g_c + hrow) = c4;
        split_store4(g_hh + hrow, g_hl + hrow, h4);
        hs = add4(hs, h4);
    }
    if (n >= 2) {
        size_t srow = ((size_t)bb * LVH + t) * 256 + d;
        split_store4(g_sh + srow, g_sl + srow, hs);
    }
}

// ---------------- output ----------------------------------------------------
__global__ void out_k(float* __restrict__ out) {
    int idx = blockIdx.x * blockDim.x + threadIdx.x;
    if (idx >= BATCH * 2 * DH) return;
    int bb = idx / (2 * DH);
    int d  = idx % (2 * DH);
    size_t row = (size_t)bb * NNODE;
    if (d < DH)
        out[idx] = __bfloat162float(g_hh[row * 256 + d]) + __bfloat162float(g_hl[row * 256 + d]);
    else
        out[idx] = g_c[row * 256 + (d - DH)];
}

// ---------------- launch ----------------------------------------------------
extern "C" void kernel_launch(void* const* d_in, const int* in_sizes, int n_in,
                              void* d_out, int out_size) {
    const float* x     = (const float*)d_in[0];
    const float* W_iou = (const float*)d_in[1];
    const float* b_iou = (const float*)d_in[2];
    const float* U_iou = (const float*)d_in[3];
    const float* W_f   = (const float*)d_in[4];
    const float* b_f   = (const float*)d_in[5];
    const float* U_f   = (const float*)d_in[6];
    float* out = (float*)d_out;

    cudaFuncSetAttribute(gemm_mma, cudaFuncAttributeMaxDynamicSharedMemorySize, SMEM_DYN);

    pack_weights<<<(NC * 256 + 255) / 256, 256>>>(W_iou, W_f, U_iou, U_f);
    {
        size_t n4 = (size_t)TOTAL_ROWS * 256 / 4;
        split_x<<<(unsigned)((n4 + 255) / 256), 256>>>(x);
    }

    // input projection for ALL nodes (unchanged from R12 winner)
    {
        dim3 grid(8, (TOTAL_ROWS + TBM - 1) / TBM);
        gemm_mma<<<grid, 256, SMEM_DYN>>>(0, 0, 0, TOTAL_ROWS, TOTAL_ROWS, 0, 0,
                                          0, 0, NC, TOTAL_ROWS);
    }

    // leaves (pairs; also writes h-sum for n=8192)
    leaf_pair<<<BATCH * LVH * 64 / 256, 256>>>(b_iou);

    // levels, bottom-up: iou-GEMM on h-sums + f-GEMM on children + combine
    for (int n = LVH; n >= 1; n >>= 1) {
        int Miou = BATCH * n;
        dim3 giou(6, (Miou + TBM - 1) / TBM);
        gemm_mma<<<giou, 256, SMEM_DYN>>>(2, 1, 1, Miou, n, 0, LVH,
                                          0, 0, 768, n);
        int Mf = BATCH * 2 * n;
        dim3 gf(2, (Mf + TBM - 1) / TBM);
        gemm_mma<<<gf, 256, SMEM_DYN>>>(1, 1, 2, Mf, 2 * n, 2 * n - 1, NNODE,
                                        768, 0, 256, 2 * n);
        int half = (n >= 2) ? (n >> 1) : 1;
        int total = BATCH * half * 64;
        combine_pair<<<(total + 255) / 256, 256>>>(b_iou, b_f, n);
    }

    out_k<<<(BATCH * 2 * DH + 255) / 256, 256>>>(out);
}

// round 15
// speedup vs baseline: 1.3257x; 1.0787x over previous
#include <cuda_runtime.h>
#include <cuda_bf16.h>
#include <cuda_fp16.h>
#include <math.h>
#include <stdint.h>

// Problem constants
#define BATCH 8
#define LV    16384
#define LVH   8192
#define NNODE 32767
#define NINT  16383
#define DH    256
#define NC    1024
#define TOTAL_ROWS (BATCH * NNODE)   // 262136

// GEMM tiling (proven: 3 stages, 96KB -> 2 CTAs/SM)
#define TBM 128
#define TBN 128
#define NSTAGE 3
#define STG_BYTES 32768       // Ah(8K) Al(8K) Bh(8K) Bl(8K)
#define SMEM_DYN (NSTAGE * STG_BYTES)

// ---------------- scratch (device globals) ----------------------------------
__device__ __nv_bfloat16 g_Wh[NC * 256];
__device__ __nv_bfloat16 g_Wl[NC * 256];
__device__ __nv_bfloat16 g_Uh[NC * 256];
__device__ __nv_bfloat16 g_Ul[NC * 256];
__device__ __nv_bfloat16 g_xh[(size_t)TOTAL_ROWS * 256];
__device__ __nv_bfloat16 g_xl[(size_t)TOTAL_ROWS * 256];
__device__ __nv_bfloat16 g_hh[(size_t)TOTAL_ROWS * 256];
__device__ __nv_bfloat16 g_hl[(size_t)TOTAL_ROWS * 256];
__device__ __nv_bfloat16 g_sh[(size_t)BATCH * LVH * 256];   // sibling h-sum hi
__device__ __nv_bfloat16 g_sl[(size_t)BATCH * LVH * 256];   // sibling h-sum lo
__device__ __half g_xproj[(size_t)TOTAL_ROWS * NC];         // fp16 preactivations
__device__ float  g_c[(size_t)TOTAL_ROWS * 256];
__device__ __half g_Riou[(size_t)BATCH * LVH * 768];        // hsum @ U_iou
__device__ __half g_Rf[(size_t)BATCH * LV * 256];           // h_child @ U_f

__device__ __forceinline__ float sigm(float x) { return 1.0f / (1.0f + expf(-x)); }

// ---------------- PTX helpers ------------------------------------------------
__device__ __forceinline__ uint32_t smem_u32(const void* p) {
    uint32_t a;
    asm("{ .reg .u64 t; cvta.to.shared.u64 t, %1; cvt.u32.u64 %0, t; }" : "=r"(a) : "l"(p));
    return a;
}
__device__ __forceinline__ void ldsm4(uint32_t& r0, uint32_t& r1, uint32_t& r2, uint32_t& r3, uint32_t addr) {
    asm volatile("ldmatrix.sync.aligned.m8n8.x4.shared.b16 {%0,%1,%2,%3},[%4];"
                 : "=r"(r0), "=r"(r1), "=r"(r2), "=r"(r3) : "r"(addr));
}
__device__ __forceinline__ void mma16816(float* c, const uint32_t* a, uint32_t b0, uint32_t b1) {
    asm volatile("mma.sync.aligned.m16n8k16.row.col.f32.bf16.bf16.f32 "
                 "{%0,%1,%2,%3},{%4,%5,%6,%7},{%8,%9},{%0,%1,%2,%3};"
                 : "+f"(c[0]), "+f"(c[1]), "+f"(c[2]), "+f"(c[3])
                 : "r"(a[0]), "r"(a[1]), "r"(a[2]), "r"(a[3]), "r"(b0), "r"(b1));
}
__device__ __forceinline__ void cp16(uint32_t dst, const void* src, int srcsz) {
    asm volatile("cp.async.cg.shared.global [%0], [%1], 16, %2;" :: "r"(dst), "l"(src), "r"(srcsz) : "memory");
}
#define CP_COMMIT() asm volatile("cp.async.commit_group;" ::: "memory")
#define CP_WAIT(n)  asm volatile("cp.async.wait_group %0;" :: "n"(n) : "memory")

__device__ __forceinline__ uint32_t swz(int r, int c) {
    return (uint32_t)(r * 64 + ((c ^ ((r >> 1) & 3)) << 4));
}
__device__ __forceinline__ void split_store4(__nv_bfloat16* hi, __nv_bfloat16* lo, float4 v) {
    __nv_bfloat16 a = __float2bfloat16_rn(v.x), b = __float2bfloat16_rn(v.y),
                  c = __float2bfloat16_rn(v.z), e = __float2bfloat16_rn(v.w);
    *(__nv_bfloat162*)(hi)     = __nv_bfloat162(a, b);
    *(__nv_bfloat162*)(hi + 2) = __nv_bfloat162(c, e);
    *(__nv_bfloat162*)(lo)     = __nv_bfloat162(__float2bfloat16_rn(v.x - __bfloat162float(a)),
                                                __float2bfloat16_rn(v.y - __bfloat162float(b)));
    *(__nv_bfloat162*)(lo + 2) = __nv_bfloat162(__float2bfloat16_rn(v.z - __bfloat162float(c)),
                                                __float2bfloat16_rn(v.w - __bfloat162float(e)));
}
__device__ __forceinline__ float4 add4(float4 a, float4 b) {
    return make_float4(a.x + b.x, a.y + b.y, a.z + b.z, a.w + b.w);
}
__device__ __forceinline__ float4 ld4h(const __half* p) {
    __half2 a = *(const __half2*)p;
    __half2 b = *(const __half2*)(p + 2);
    return make_float4(__low2float(a), __high2float(a), __low2float(b), __high2float(b));
}

// ---------------- weight packing ---------------------------------------------
__global__ void pack_weights(const float* __restrict__ W_iou, const float* __restrict__ W_f,
                             const float* __restrict__ U_iou, const float* __restrict__ U_f) {
    int idx = blockIdx.x * blockDim.x + threadIdx.x;
    if (idx >= NC * 256) return;
    int j = idx / 256, k = idx % 256;
    float wv = (j < 768) ? W_iou[k * 768 + j] : W_f[k * 256 + (j - 768)];
    float uv = (j < 768) ? U_iou[k * 768 + j] : U_f[k * 256 + (j - 768)];
    __nv_bfloat16 wh = __float2bfloat16_rn(wv);
    g_Wh[idx] = wh;
    g_Wl[idx] = __float2bfloat16_rn(wv - __bfloat162float(wh));
    __nv_bfloat16 uh = __float2bfloat16_rn(uv);
    g_Uh[idx] = uh;
    g_Ul[idx] = __float2bfloat16_rn(uv - __bfloat162float(uh));
}

// ---------------- x hi/lo split ----------------------------------------------
__global__ void split_x(const float* __restrict__ x) {
    size_t i = (size_t)blockIdx.x * blockDim.x + threadIdx.x;
    const size_t n4 = (size_t)TOTAL_ROWS * 256 / 4;
    if (i >= n4) return;
    float4 v = ((const float4*)x)[i];
    split_store4(g_xh + 4 * i, g_xl + 4 * i, v);
}

// ---------------- shared GEMM body (3-term bf16 split, 128x128x256) ----------
__device__ __forceinline__ void gemm_body(
    const __nv_bfloat16* __restrict__ Ahg, const __nv_bfloat16* __restrict__ Alg,
    const __nv_bfloat16* __restrict__ Bhg, const __nv_bfloat16* __restrict__ Blg,
    __half* __restrict__ C, int M, int rpb, int row_off, int node_stride,
    int row0, int col0, int ccol0, int ldc, int cns, uint32_t sb)
{
    const int tid = threadIdx.x, wid = tid >> 5, lane = tid & 31;
    const int wm = wid >> 2, wn = wid & 3;

    const int lr = tid >> 1;
    const int c2 = (tid & 1) * 2;
    size_t aoff; int asz;
    {
        int m = row0 + lr;
        if (m < M) {
            int bb = m / rpb, loc = m - bb * rpb;
            aoff = ((size_t)bb * node_stride + (size_t)(row_off + loc)) * 256;
            asz = 16;
        } else { aoff = 0; asz = 0; }
    }
    const size_t boff = (size_t)(col0 + lr) * 256;
    const uint32_t s0 = swz(lr, c2), s1 = swz(lr, c2 + 1);

#define LOAD_CHUNK(kc, st) do {                                               \
        uint32_t bs = sb + (uint32_t)(st) * STG_BYTES;                        \
        int kg = (kc) * 32;                                                   \
        cp16(bs + s0,          Ahg + aoff + kg + c2 * 8,       asz);          \
        cp16(bs + s1,          Ahg + aoff + kg + c2 * 8 + 8,   asz);          \
        cp16(bs + 8192 + s0,   Alg + aoff + kg + c2 * 8,       asz);          \
        cp16(bs + 8192 + s1,   Alg + aoff + kg + c2 * 8 + 8,   asz);          \
        cp16(bs + 16384 + s0,  Bhg + boff + kg + c2 * 8,       16);           \
        cp16(bs + 16384 + s1,  Bhg + boff + kg + c2 * 8 + 8,   16);           \
        cp16(bs + 24576 + s0,  Blg + boff + kg + c2 * 8,       16);           \
        cp16(bs + 24576 + s1,  Blg + boff + kg + c2 * 8 + 8,   16);           \
        CP_COMMIT();                                                          \
    } while (0)

    float acc[4][4][4];
#pragma unroll
    for (int mt = 0; mt < 4; mt++)
#pragma unroll
        for (int nt = 0; nt < 4; nt++)
#pragma unroll
            for (int e = 0; e < 4; e++) acc[mt][nt][e] = 0.0f;

#define COMPUTE_CHUNK(st) do {                                                \
        uint32_t cb = sb + (uint32_t)(st) * STG_BYTES;                        \
        _Pragma("unroll")                                                     \
        for (int ks = 0; ks < 2; ks++) {                                      \
            uint32_t ah[4][4], al[4][4];                                      \
            int cch = ks * 2 + (lane >> 4);                                   \
            _Pragma("unroll")                                                 \
            for (int mt = 0; mt < 4; mt++) {                                  \
                int mr = wm * 64 + mt * 16 + (lane & 15);                     \
                uint32_t ad = cb + swz(mr, cch);                              \
                ldsm4(ah[mt][0], ah[mt][1], ah[mt][2], ah[mt][3], ad);        \
                ldsm4(al[mt][0], al[mt][1], al[mt][2], al[mt][3], ad + 8192); \
            }                                                                 \
            _Pragma("unroll")                                                 \
            for (int nt2 = 0; nt2 < 2; nt2++) {                               \
                int nr = wn * 32 + nt2 * 16 + (lane & 15);                    \
                uint32_t bd = cb + 16384 + swz(nr, cch);                      \
                uint32_t bh[4], bl[4];                                        \
                ldsm4(bh[0], bh[1], bh[2], bh[3], bd);                        \
                ldsm4(bl[0], bl[1], bl[2], bl[3], bd + 8192);                 \
                _Pragma("unroll")                                             \
                for (int mt = 0; mt < 4; mt++) {                              \
                    mma16816(acc[mt][nt2 * 2],     ah[mt], bh[0], bh[2]);     \
                    mma16816(acc[mt][nt2 * 2],     ah[mt], bl[0], bl[2]);     \
                    mma16816(acc[mt][nt2 * 2],     al[mt], bh[0], bh[2]);     \
                    mma16816(acc[mt][nt2 * 2 + 1], ah[mt], bh[1], bh[3]);     \
                    mma16816(acc[mt][nt2 * 2 + 1], ah[mt], bl[1], bl[3]);     \
                    mma16816(acc[mt][nt2 * 2 + 1], al[mt], bh[1], bh[3]);     \
                }                                                             \
            }                                                                 \
        }                                                                     \
    } while (0)

    LOAD_CHUNK(0, 0);
    LOAD_CHUNK(1, 1);
    LOAD_CHUNK(2, 2);

    int st_c = 0;
#pragma unroll 1
    for (int kc = 0; kc < 6; kc++) {
        CP_WAIT(2);
        __syncthreads();
        COMPUTE_CHUNK(st_c);
        if (kc < 5) {
            __syncthreads();
            LOAD_CHUNK(kc + 3, st_c);
        }
        st_c = (st_c == 2) ? 0 : st_c + 1;
    }
    CP_WAIT(1); __syncthreads();
    COMPUTE_CHUNK(st_c);
    st_c = (st_c == 2) ? 0 : st_c + 1;
    CP_WAIT(0); __syncthreads();
    COMPUTE_CHUNK(st_c);

    // epilogue (fp16 stores, remapped C rows)
#pragma unroll
    for (int mt = 0; mt < 4; mt++) {
        int r_lo = row0 + wm * 64 + mt * 16 + (lane >> 2);
        int r_hi = r_lo + 8;
#pragma unroll
        for (int nt = 0; nt < 4; nt++) {
            int cc = ccol0 + wn * 32 + nt * 8 + 2 * (lane & 3);
            if (r_lo < M) {
                int bb = r_lo / rpb, loc = r_lo - bb * rpb;
                *(__half2*)(&C[((size_t)bb * cns + loc) * ldc + cc]) =
                    __floats2half2_rn(acc[mt][nt][0], acc[mt][nt][1]);
            }
            if (r_hi < M) {
                int bb = r_hi / rpb, loc = r_hi - bb * rpb;
                *(__half2*)(&C[((size_t)bb * cns + loc) * ldc + cc]) =
                    __floats2half2_rn(acc[mt][nt][2], acc[mt][nt][3]);
            }
        }
    }
#undef LOAD_CHUNK
#undef COMPUTE_CHUNK
}

// ---------------- input projection GEMM (all nodes, 1024 cols) ---------------
__global__ __launch_bounds__(256, 2)
void gemm_input()
{
    extern __shared__ char smem[];
    gemm_body(g_xh, g_xl, g_Wh, g_Wl, g_xproj,
              TOTAL_ROWS, TOTAL_ROWS, 0, 0,
              blockIdx.y * TBM, blockIdx.x * TBN, blockIdx.x * TBN,
              NC, TOTAL_ROWS, smem_u32(smem));
}

// ---------------- merged recurrent GEMM: iou (h-sums) + f (children) ---------
// Flattened exact grid: first 6*tiy tiles = iou region, rest = f region.
__global__ __launch_bounds__(256, 2)
void gemm_rec(int n)
{
    extern __shared__ char smem[];
    const uint32_t sb = smem_u32(smem);
    const int tiy = (8 * n + TBM - 1) / TBM;
    const int flat = blockIdx.x;
    if (flat < 6 * tiy) {
        int tx = flat % 6, ty = flat / 6;
        gemm_body(g_sh, g_sl, g_Uh, g_Ul, g_Riou,
                  8 * n, n, 0, LVH,
                  ty * TBM, tx * TBN, tx * TBN, 768, n, sb);
    } else {
        int rem = flat - 6 * tiy;
        int tx = rem & 1, ty = rem >> 1;
        gemm_body(g_hh, g_hl, g_Uh, g_Ul, g_Rf,
                  16 * n, 2 * n, 2 * n - 1, NNODE,
                  ty * TBM, 768 + tx * TBN, tx * TBN, 256, 2 * n, sb);
    }
}

// ---------------- leaf pairs: gates + h-sum for n=8192 parents ---------------
__global__ void leaf_pair(const float* __restrict__ b_iou) {
    int gid = blockIdx.x * blockDim.x + threadIdx.x;
    const int total = BATCH * LVH * 64;
    if (gid >= total) return;
    int d = (gid & 63) << 2;
    int rest = gid >> 6;
    int t = rest & (LVH - 1);
    int bb = rest >> 13;

    float4 bi = *(const float4*)(b_iou + d);
    float4 bo = *(const float4*)(b_iou + 256 + d);
    float4 bu = *(const float4*)(b_iou + 512 + d);

    float4 hs = make_float4(0.f, 0.f, 0.f, 0.f);
#pragma unroll
    for (int s = 0; s < 2; s++) {
        size_t row = (size_t)bb * NNODE + NINT + 2 * t + s;
        const __half* xp = g_xproj + row * NC;
        float4 i4 = add4(ld4h(xp + d), bi);
        float4 o4 = add4(ld4h(xp + 256 + d), bo);
        float4 u4 = add4(ld4h(xp + 512 + d), bu);
        float4 c4, h4;
        c4.x = sigm(i4.x) * tanhf(u4.x); h4.x = sigm(o4.x) * tanhf(c4.x);
        c4.y = sigm(i4.y) * tanhf(u4.y); h4.y = sigm(o4.y) * tanhf(c4.y);
        c4.z = sigm(i4.z) * tanhf(u4.z); h4.z = sigm(o4.z) * tanhf(c4.z);
        c4.w = sigm(i4.w) * tanhf(u4.w); h4.w = sigm(o4.w) * tanhf(c4.w);
        size_t hrow = row * 256 + d;
        *(float4*)(g_c + hrow) = c4;
        split_store4(g_hh + hrow, g_hl + hrow, h4);
        hs = add4(hs, h4);
    }
    size_t srow = ((size_t)bb * LVH + t) * 256 + d;
    split_store4(g_sh + srow, g_sl + srow, hs);
}

// ---------------- combine pairs: level n parents + next h-sum ----------------
__global__ void combine_pair(const float* __restrict__ b_iou, const float* __restrict__ b_f, int n) {
    int gid = blockIdx.x * blockDim.x + threadIdx.x;
    const int half = n >> 1;
    const int total = BATCH * half * 64;
    if (gid >= total) return;
    int d = (gid & 63) << 2;
    int rest = gid >> 6;
    int t = rest % half;
    int bb = rest / half;

    float4 bi = *(const float4*)(b_iou + d);
    float4 bo = *(const float4*)(b_iou + 256 + d);
    float4 bu = *(const float4*)(b_iou + 512 + d);
    float4 bf = *(const float4*)(b_f + d);

    float4 hs = make_float4(0.f, 0.f, 0.f, 0.f);
#pragma unroll
    for (int s = 0; s < 2; s++) {
        int k = 2 * t + s;
        int j = n - 1 + k;
        size_t row = (size_t)bb * NNODE + j;
        const __half* xp = g_xproj + row * NC;
        const __half* Ri = g_Riou + ((size_t)bb * n + k) * 768;
        const __half* Rf0 = g_Rf + ((size_t)bb * 2 * n + 2 * k) * 256;
        const __half* Rf1 = Rf0 + 256;

        float4 i4 = add4(add4(ld4h(xp + d),       ld4h(Ri + d)),       bi);
        float4 o4 = add4(add4(ld4h(xp + 256 + d), ld4h(Ri + 256 + d)), bo);
        float4 u4 = add4(add4(ld4h(xp + 512 + d), ld4h(Ri + 512 + d)), bu);
        float4 fx = add4(ld4h(xp + 768 + d), bf);
        float4 f0 = ld4h(Rf0 + d);
        float4 f1 = ld4h(Rf1 + d);

        size_t crow = ((size_t)bb * NNODE + 2 * j + 1) * 256 + d;
        float4 c0 = *(const float4*)(g_c + crow);
        float4 c1 = *(const float4*)(g_c + crow + 256);

        float4 c4, h4;
        c4.x = sigm(i4.x) * tanhf(u4.x) + sigm(fx.x + f0.x) * c0.x + sigm(fx.x + f1.x) * c1.x;
        c4.y = sigm(i4.y) * tanhf(u4.y) + sigm(fx.y + f0.y) * c0.y + sigm(fx.y + f1.y) * c1.y;
        c4.z = sigm(i4.z) * tanhf(u4.z) + sigm(fx.z + f0.z) * c0.z + sigm(fx.z + f1.z) * c1.z;
        c4.w = sigm(i4.w) * tanhf(u4.w) + sigm(fx.w + f0.w) * c0.w + sigm(fx.w + f1.w) * c1.w;
        h4.x = sigm(o4.x) * tanhf(c4.x);
        h4.y = sigm(o4.y) * tanhf(c4.y);
        h4.z = sigm(o4.z) * tanhf(c4.z);
        h4.w = sigm(o4.w) * tanhf(c4.w);

        size_t hrow = row * 256 + d;
        *(float4*)(g_c + hrow) = c4;
        split_store4(g_hh + hrow, g_hl + hrow, h4);
        hs = add4(hs, h4);
    }
    size_t srow = ((size_t)bb * LVH + t) * 256 + d;
    split_store4(g_sh + srow, g_sl + srow, hs);
}

// ---------------- fused small level (n <= 64): one block per parent ----------
__global__ void level_small(const float* __restrict__ b_iou, const float* __restrict__ b_f,
                            const float* __restrict__ U_iou, const float* __restrict__ U_f,
                            int n, float* __restrict__ out) {
    __shared__ float h0s[256], h1s[256], hss[256];
    int blk = blockIdx.x;               // bb * n + k
    int bb = blk / n, k = blk - bb * n;
    int j = n - 1 + k;
    int d = threadIdx.x;

    size_t rc = ((size_t)bb * NNODE + 2 * j + 1) * 256;   // child0 row base
    float h0 = __bfloat162float(g_hh[rc + d]) + __bfloat162float(g_hl[rc + d]);
    float h1 = __bfloat162float(g_hh[rc + 256 + d]) + __bfloat162float(g_hl[rc + 256 + d]);
    h0s[d] = h0; h1s[d] = h1; hss[d] = h0 + h1;
    __syncthreads();

    float ai = 0.f, ao = 0.f, au = 0.f, af0 = 0.f, af1 = 0.f;
#pragma unroll 8
    for (int kk = 0; kk < 256; kk++) {
        float hsv = hss[kk], a0 = h0s[kk], a1 = h1s[kk];
        const float* Ur = U_iou + kk * 768 + d;
        ai = fmaf(hsv, Ur[0], ai);
        ao = fmaf(hsv, Ur[256], ao);
        au = fmaf(hsv, Ur[512], au);
        float wf = U_f[kk * 256 + d];
        af0 = fmaf(a0, wf, af0);
        af1 = fmaf(a1, wf, af1);
    }

    const __half* xp = g_xproj + ((size_t)bb * NNODE + j) * NC;
    float iv = __half2float(xp[d])       + b_iou[d]       + ai;
    float ov = __half2float(xp[256 + d]) + b_iou[256 + d] + ao;
    float uv = __half2float(xp[512 + d]) + b_iou[512 + d] + au;
    float fx = __half2float(xp[768 + d]) + b_f[d];
    float c0 = g_c[rc + d], c1 = g_c[rc + 256 + d];
    float cv = sigm(iv) * tanhf(uv) + sigm(fx + af0) * c0 + sigm(fx + af1) * c1;
    float hv = sigm(ov) * tanhf(cv);

    size_t hrow = ((size_t)bb * NNODE + j) * 256 + d;
    g_c[hrow] = cv;
    __nv_bfloat16 hh = __float2bfloat16_rn(hv);
    g_hh[hrow] = hh;
    g_hl[hrow] = __float2bfloat16_rn(hv - __bfloat162float(hh));

    if (n == 1) {
        out[bb * 512 + d] = hv;
        out[bb * 512 + 256 + d] = cv;
    }
}

// ---------------- launch ----------------------------------------------------
extern "C" void kernel_launch(void* const* d_in, const int* in_sizes, int n_in,
                              void* d_out, int out_size) {
    const float* x     = (const float*)d_in[0];
    const float* W_iou = (const float*)d_in[1];
    const float* b_iou = (const float*)d_in[2];
    const float* U_iou = (const float*)d_in[3];
    const float* W_f   = (const float*)d_in[4];
    const float* b_f   = (const float*)d_in[5];
    const float* U_f   = (const float*)d_in[6];
    float* out = (float*)d_out;

    cudaFuncSetAttribute(gemm_input, cudaFuncAttributeMaxDynamicSharedMemorySize, SMEM_DYN);
    cudaFuncSetAttribute(gemm_rec,   cudaFuncAttributeMaxDynamicSharedMemorySize, SMEM_DYN);

    pack_weights<<<(NC * 256 + 255) / 256, 256>>>(W_iou, W_f, U_iou, U_f);
    {
        size_t n4 = (size_t)TOTAL_ROWS * 256 / 4;
        split_x<<<(unsigned)((n4 + 255) / 256), 256>>>(x);
    }

    // input projection for ALL nodes
    {
        dim3 grid(8, (TOTAL_ROWS + TBM - 1) / TBM);
        gemm_input<<<grid, 256, SMEM_DYN>>>();
    }

    // leaves (pairs; also writes h-sum for n=8192)
    leaf_pair<<<BATCH * LVH * 64 / 256, 256>>>(b_iou);

    // big levels: merged iou+f recurrent GEMM (exact flattened grid) + combine
    for (int n = LVH; n >= 128; n >>= 1) {
        int tiy = (8 * n + TBM - 1) / TBM;
        int tfy = (16 * n + TBM - 1) / TBM;
        gemm_rec<<<6 * tiy + 2 * tfy, 256, SMEM_DYN>>>(n);
        int total = BATCH * (n >> 1) * 64;
        combine_pair<<<(total + 255) / 256, 256>>>(b_iou, b_f, n);
    }

    // small levels fused (n = 64 .. 1); n==1 writes out
    for (int n = 64; n >= 1; n >>= 1)
        level_small<<<BATCH * n, 256>>>(b_iou, b_f, U_iou, U_f, n, out);
}

// round 16
// speedup vs baseline: 1.3925x; 1.0504x over previous
#include <cuda_runtime.h>
#include <cuda_bf16.h>
#include <cuda_fp16.h>
#include <math.h>
#include <stdint.h>

// Problem constants
#define BATCH 8
#define LV    16384
#define LVH   8192
#define NNODE 32767
#define NINT  16383
#define DH    256
#define NC    1024
#define TOTAL_ROWS (BATCH * NNODE)   // 262136

// GEMM tiling (proven: 3 stages, 96KB -> 2 CTAs/SM)
#define TBM 128
#define TBN 128
#define NSTAGE 3
#define STG_BYTES 32768       // Ah(8K) Al(8K) Bh(8K) Bl(8K)
#define SMEM_DYN (NSTAGE * STG_BYTES)

// ---------------- scratch (device globals) ----------------------------------
__device__ __nv_bfloat16 g_Wh[NC * 256];
__device__ __nv_bfloat16 g_Wl[NC * 256];
__device__ __nv_bfloat16 g_Uh[NC * 256];
__device__ __nv_bfloat16 g_Ul[NC * 256];
__device__ __nv_bfloat16 g_xh[(size_t)TOTAL_ROWS * 256];
__device__ __nv_bfloat16 g_xl[(size_t)TOTAL_ROWS * 256];
__device__ __nv_bfloat16 g_hh[(size_t)TOTAL_ROWS * 256];
__device__ __nv_bfloat16 g_hl[(size_t)TOTAL_ROWS * 256];
__device__ __nv_bfloat16 g_sh[(size_t)BATCH * LVH * 256];   // sibling h-sum hi
__device__ __nv_bfloat16 g_sl[(size_t)BATCH * LVH * 256];   // sibling h-sum lo
__device__ __half g_xproj[(size_t)TOTAL_ROWS * NC];         // fp16 preactivations
__device__ float  g_c[(size_t)TOTAL_ROWS * 256];
__device__ __half g_Riou[(size_t)BATCH * LVH * 768];        // hsum @ U_iou
__device__ __half g_Rf[(size_t)BATCH * LV * 256];           // h_child @ U_f

__device__ __forceinline__ float sigm(float x) { return 1.0f / (1.0f + expf(-x)); }

// ---------------- PTX helpers ------------------------------------------------
__device__ __forceinline__ uint32_t smem_u32(const void* p) {
    uint32_t a;
    asm("{ .reg .u64 t; cvta.to.shared.u64 t, %1; cvt.u32.u64 %0, t; }" : "=r"(a) : "l"(p));
    return a;
}
__device__ __forceinline__ void ldsm4(uint32_t& r0, uint32_t& r1, uint32_t& r2, uint32_t& r3, uint32_t addr) {
    asm volatile("ldmatrix.sync.aligned.m8n8.x4.shared.b16 {%0,%1,%2,%3},[%4];"
                 : "=r"(r0), "=r"(r1), "=r"(r2), "=r"(r3) : "r"(addr));
}
__device__ __forceinline__ void mma16816(float* c, const uint32_t* a, uint32_t b0, uint32_t b1) {
    asm volatile("mma.sync.aligned.m16n8k16.row.col.f32.bf16.bf16.f32 "
                 "{%0,%1,%2,%3},{%4,%5,%6,%7},{%8,%9},{%0,%1,%2,%3};"
                 : "+f"(c[0]), "+f"(c[1]), "+f"(c[2]), "+f"(c[3])
                 : "r"(a[0]), "r"(a[1]), "r"(a[2]), "r"(a[3]), "r"(b0), "r"(b1));
}
__device__ __forceinline__ void cp16(uint32_t dst, const void* src, int srcsz) {
    asm volatile("cp.async.cg.shared.global [%0], [%1], 16, %2;" :: "r"(dst), "l"(src), "r"(srcsz) : "memory");
}
#define CP_COMMIT() asm volatile("cp.async.commit_group;" ::: "memory")
#define CP_WAIT(n)  asm volatile("cp.async.wait_group %0;" :: "n"(n) : "memory")

__device__ __forceinline__ uint32_t swz(int r, int c) {
    return (uint32_t)(r * 64 + ((c ^ ((r >> 1) & 3)) << 4));
}
__device__ __forceinline__ void split_store4(__nv_bfloat16* hi, __nv_bfloat16* lo, float4 v) {
    __nv_bfloat16 a = __float2bfloat16_rn(v.x), b = __float2bfloat16_rn(v.y),
                  c = __float2bfloat16_rn(v.z), e = __float2bfloat16_rn(v.w);
    *(__nv_bfloat162*)(hi)     = __nv_bfloat162(a, b);
    *(__nv_bfloat162*)(hi + 2) = __nv_bfloat162(c, e);
    *(__nv_bfloat162*)(lo)     = __nv_bfloat162(__float2bfloat16_rn(v.x - __bfloat162float(a)),
                                                __float2bfloat16_rn(v.y - __bfloat162float(b)));
    *(__nv_bfloat162*)(lo + 2) = __nv_bfloat162(__float2bfloat16_rn(v.z - __bfloat162float(c)),
                                                __float2bfloat16_rn(v.w - __bfloat162float(e)));
}
__device__ __forceinline__ float4 add4(float4 a, float4 b) {
    return make_float4(a.x + b.x, a.y + b.y, a.z + b.z, a.w + b.w);
}
__device__ __forceinline__ float4 ld4h(const __half* p) {
    __half2 a = *(const __half2*)p;
    __half2 b = *(const __half2*)(p + 2);
    return make_float4(__low2float(a), __high2float(a), __low2float(b), __high2float(b));
}

// ---------------- weight packing ---------------------------------------------
__global__ void pack_weights(const float* __restrict__ W_iou, const float* __restrict__ W_f,
                             const float* __restrict__ U_iou, const float* __restrict__ U_f) {
    int idx = blockIdx.x * blockDim.x + threadIdx.x;
    if (idx >= NC * 256) return;
    int j = idx / 256, k = idx % 256;
    float wv = (j < 768) ? W_iou[k * 768 + j] : W_f[k * 256 + (j - 768)];
    float uv = (j < 768) ? U_iou[k * 768 + j] : U_f[k * 256 + (j - 768)];
    __nv_bfloat16 wh = __float2bfloat16_rn(wv);
    g_Wh[idx] = wh;
    g_Wl[idx] = __float2bfloat16_rn(wv - __bfloat162float(wh));
    __nv_bfloat16 uh = __float2bfloat16_rn(uv);
    g_Uh[idx] = uh;
    g_Ul[idx] = __float2bfloat16_rn(uv - __bfloat162float(uh));
}

// ---------------- x hi/lo split ----------------------------------------------
__global__ void split_x(const float* __restrict__ x) {
    size_t i = (size_t)blockIdx.x * blockDim.x + threadIdx.x;
    const size_t n4 = (size_t)TOTAL_ROWS * 256 / 4;
    if (i >= n4) return;
    float4 v = ((const float4*)x)[i];
    split_store4(g_xh + 4 * i, g_xl + 4 * i, v);
}

// ---------------- shared GEMM body (3-term bf16 split, 128x128x256) ----------
__device__ __forceinline__ void gemm_body(
    const __nv_bfloat16* __restrict__ Ahg, const __nv_bfloat16* __restrict__ Alg,
    const __nv_bfloat16* __restrict__ Bhg, const __nv_bfloat16* __restrict__ Blg,
    __half* __restrict__ C, int M, int rpb, int row_off, int node_stride,
    int row0, int col0, int ccol0, int ldc, int cns, uint32_t sb)
{
    const int tid = threadIdx.x, wid = tid >> 5, lane = tid & 31;
    const int wm = wid >> 2, wn = wid & 3;

    const int lr = tid >> 1;
    const int c2 = (tid & 1) * 2;
    size_t aoff; int asz;
    {
        int m = row0 + lr;
        if (m < M) {
            int bb = m / rpb, loc = m - bb * rpb;
            aoff = ((size_t)bb * node_stride + (size_t)(row_off + loc)) * 256;
            asz = 16;
        } else { aoff = 0; asz = 0; }
    }
    const size_t boff = (size_t)(col0 + lr) * 256;
    const uint32_t s0 = swz(lr, c2), s1 = swz(lr, c2 + 1);

#define LOAD_CHUNK(kc, st) do {                                               \
        uint32_t bs = sb + (uint32_t)(st) * STG_BYTES;                        \
        int kg = (kc) * 32;                                                   \
        cp16(bs + s0,          Ahg + aoff + kg + c2 * 8,       asz);          \
        cp16(bs + s1,          Ahg + aoff + kg + c2 * 8 + 8,   asz);          \
        cp16(bs + 8192 + s0,   Alg + aoff + kg + c2 * 8,       asz);          \
        cp16(bs + 8192 + s1,   Alg + aoff + kg + c2 * 8 + 8,   asz);          \
        cp16(bs + 16384 + s0,  Bhg + boff + kg + c2 * 8,       16);           \
        cp16(bs + 16384 + s1,  Bhg + boff + kg + c2 * 8 + 8,   16);           \
        cp16(bs + 24576 + s0,  Blg + boff + kg + c2 * 8,       16);           \
        cp16(bs + 24576 + s1,  Blg + boff + kg + c2 * 8 + 8,   16);           \
        CP_COMMIT();                                                          \
    } while (0)

    float acc[4][4][4];
#pragma unroll
    for (int mt = 0; mt < 4; mt++)
#pragma unroll
        for (int nt = 0; nt < 4; nt++)
#pragma unroll
            for (int e = 0; e < 4; e++) acc[mt][nt][e] = 0.0f;

#define COMPUTE_CHUNK(st) do {                                                \
        uint32_t cb = sb + (uint32_t)(st) * STG_BYTES;                        \
        _Pragma("unroll")                                                     \
        for (int ks = 0; ks < 2; ks++) {                                      \
            uint32_t ah[4][4], al[4][4];                                      \
            int cch = ks * 2 + (lane >> 4);                                   \
            _Pragma("unroll")                                                 \
            for (int mt = 0; mt < 4; mt++) {                                  \
                int mr = wm * 64 + mt * 16 + (lane & 15);                     \
                uint32_t ad = cb + swz(mr, cch);                              \
                ldsm4(ah[mt][0], ah[mt][1], ah[mt][2], ah[mt][3], ad);        \
                ldsm4(al[mt][0], al[mt][1], al[mt][2], al[mt][3], ad + 8192); \
            }                                                                 \
            _Pragma("unroll")                                                 \
            for (int nt2 = 0; nt2 < 2; nt2++) {                               \
                int nr = wn * 32 + nt2 * 16 + (lane & 15);                    \
                uint32_t bd = cb + 16384 + swz(nr, cch);                      \
                uint32_t bh[4], bl[4];                                        \
                ldsm4(bh[0], bh[1], bh[2], bh[3], bd);                        \
                ldsm4(bl[0], bl[1], bl[2], bl[3], bd + 8192);                 \
                _Pragma("unroll")                                             \
                for (int mt = 0; mt < 4; mt++) {                              \
                    mma16816(acc[mt][nt2 * 2],     ah[mt], bh[0], bh[2]);     \
                    mma16816(acc[mt][nt2 * 2],     ah[mt], bl[0], bl[2]);     \
                    mma16816(acc[mt][nt2 * 2],     al[mt], bh[0], bh[2]);     \
                    mma16816(acc[mt][nt2 * 2 + 1], ah[mt], bh[1], bh[3]);     \
                    mma16816(acc[mt][nt2 * 2 + 1], ah[mt], bl[1], bl[3]);     \
                    mma16816(acc[mt][nt2 * 2 + 1], al[mt], bh[1], bh[3]);     \
                }                                                             \
            }                                                                 \
        }                                                                     \
    } while (0)

    LOAD_CHUNK(0, 0);
    LOAD_CHUNK(1, 1);
    LOAD_CHUNK(2, 2);

    int st_c = 0;
#pragma unroll 1
    for (int kc = 0; kc < 6; kc++) {
        CP_WAIT(2);
        __syncthreads();
        COMPUTE_CHUNK(st_c);
        if (kc < 5) {
            __syncthreads();
            LOAD_CHUNK(kc + 3, st_c);
        }
        st_c = (st_c == 2) ? 0 : st_c + 1;
    }
    CP_WAIT(1); __syncthreads();
    COMPUTE_CHUNK(st_c);
    st_c = (st_c == 2) ? 0 : st_c + 1;
    CP_WAIT(0); __syncthreads();
    COMPUTE_CHUNK(st_c);

    // epilogue (fp16 stores, remapped C rows)
#pragma unroll
    for (int mt = 0; mt < 4; mt++) {
        int r_lo = row0 + wm * 64 + mt * 16 + (lane >> 2);
        int r_hi = r_lo + 8;
#pragma unroll
        for (int nt = 0; nt < 4; nt++) {
            int cc = ccol0 + wn * 32 + nt * 8 + 2 * (lane & 3);
            if (r_lo < M) {
                int bb = r_lo / rpb, loc = r_lo - bb * rpb;
                *(__half2*)(&C[((size_t)bb * cns + loc) * ldc + cc]) =
                    __floats2half2_rn(acc[mt][nt][0], acc[mt][nt][1]);
            }
            if (r_hi < M) {
                int bb = r_hi / rpb, loc = r_hi - bb * rpb;
                *(__half2*)(&C[((size_t)bb * cns + loc) * ldc + cc]) =
                    __floats2half2_rn(acc[mt][nt][2], acc[mt][nt][3]);
            }
        }
    }
#undef LOAD_CHUNK
#undef COMPUTE_CHUNK
}

// ---------------- input projection GEMM (merged flat grid) -------------------
// iou region: all rows x cols 0..767 (6 col-tiles).
// f   region: internal rows only x cols 768..1023 (2 col-tiles).
#define TIY_ALL ((TOTAL_ROWS + TBM - 1) / TBM)           // 2048
#define MF_IN   (BATCH * NINT)                           // 131064
#define TFY_IN  ((MF_IN + TBM - 1) / TBM)                // 1024
__global__ __launch_bounds__(256, 2)
void gemm_input()
{
    extern __shared__ char smem[];
    const uint32_t sb = smem_u32(smem);
    const int flat = blockIdx.x;
    if (flat < 6 * TIY_ALL) {
        int tx = flat % 6, ty = flat / 6;
        gemm_body(g_xh, g_xl, g_Wh, g_Wl, g_xproj,
                  TOTAL_ROWS, TOTAL_ROWS, 0, 0,
                  ty * TBM, tx * TBN, tx * TBN, NC, TOTAL_ROWS, sb);
    } else {
        int rem = flat - 6 * TIY_ALL;
        int tx = rem & 1, ty = rem >> 1;
        gemm_body(g_xh, g_xl, g_Wh, g_Wl, g_xproj,
                  MF_IN, NINT, 0, NNODE,
                  ty * TBM, 768 + tx * TBN, 768 + tx * TBN, NC, NNODE, sb);
    }
}

// ---------------- merged recurrent GEMM: iou (h-sums) + f (children) ---------
__global__ __launch_bounds__(256, 2)
void gemm_rec(int n)
{
    extern __shared__ char smem[];
    const uint32_t sb = smem_u32(smem);
    const int tiy = (8 * n + TBM - 1) / TBM;
    const int flat = blockIdx.x;
    if (flat < 6 * tiy) {
        int tx = flat % 6, ty = flat / 6;
        gemm_body(g_sh, g_sl, g_Uh, g_Ul, g_Riou,
                  8 * n, n, 0, LVH,
                  ty * TBM, tx * TBN, tx * TBN, 768, n, sb);
    } else {
        int rem = flat - 6 * tiy;
        int tx = rem & 1, ty = rem >> 1;
        gemm_body(g_hh, g_hl, g_Uh, g_Ul, g_Rf,
                  16 * n, 2 * n, 2 * n - 1, NNODE,
                  ty * TBM, 768 + tx * TBN, tx * TBN, 256, 2 * n, sb);
    }
}

// ---------------- leaf pairs: gates + h-sum for n=8192 parents ---------------
__global__ void leaf_pair(const float* __restrict__ b_iou) {
    int gid = blockIdx.x * blockDim.x + threadIdx.x;
    const int total = BATCH * LVH * 64;
    if (gid >= total) return;
    int d = (gid & 63) << 2;
    int rest = gid >> 6;
    int t = rest & (LVH - 1);
    int bb = rest >> 13;

    float4 bi = *(const float4*)(b_iou + d);
    float4 bo = *(const float4*)(b_iou + 256 + d);
    float4 bu = *(const float4*)(b_iou + 512 + d);

    float4 hs = make_float4(0.f, 0.f, 0.f, 0.f);
#pragma unroll
    for (int s = 0; s < 2; s++) {
        size_t row = (size_t)bb * NNODE + NINT + 2 * t + s;
        const __half* xp = g_xproj + row * NC;
        float4 i4 = add4(ld4h(xp + d), bi);
        float4 o4 = add4(ld4h(xp + 256 + d), bo);
        float4 u4 = add4(ld4h(xp + 512 + d), bu);
        float4 c4, h4;
        c4.x = sigm(i4.x) * tanhf(u4.x); h4.x = sigm(o4.x) * tanhf(c4.x);
        c4.y = sigm(i4.y) * tanhf(u4.y); h4.y = sigm(o4.y) * tanhf(c4.y);
        c4.z = sigm(i4.z) * tanhf(u4.z); h4.z = sigm(o4.z) * tanhf(c4.z);
        c4.w = sigm(i4.w) * tanhf(u4.w); h4.w = sigm(o4.w) * tanhf(c4.w);
        size_t hrow = row * 256 + d;
        *(float4*)(g_c + hrow) = c4;
        split_store4(g_hh + hrow, g_hl + hrow, h4);
        hs = add4(hs, h4);
    }
    size_t srow = ((size_t)bb * LVH + t) * 256 + d;
    split_store4(g_sh + srow, g_sl + srow, hs);
}

// ---------------- combine pairs: level n parents + next h-sum ----------------
__global__ void combine_pair(const float* __restrict__ b_iou, const float* __restrict__ b_f, int n) {
    int gid = blockIdx.x * blockDim.x + threadIdx.x;
    const int half = n >> 1;
    const int total = BATCH * half * 64;
    if (gid >= total) return;
    int d = (gid & 63) << 2;
    int rest = gid >> 6;
    int t = rest % half;
    int bb = rest / half;

    float4 bi = *(const float4*)(b_iou + d);
    float4 bo = *(const float4*)(b_iou + 256 + d);
    float4 bu = *(const float4*)(b_iou + 512 + d);
    float4 bf = *(const float4*)(b_f + d);

    float4 hs = make_float4(0.f, 0.f, 0.f, 0.f);
#pragma unroll
    for (int s = 0; s < 2; s++) {
        int k = 2 * t + s;
        int j = n - 1 + k;
        size_t row = (size_t)bb * NNODE + j;
        const __half* xp = g_xproj + row * NC;
        const __half* Ri = g_Riou + ((size_t)bb * n + k) * 768;
        const __half* Rf0 = g_Rf + ((size_t)bb * 2 * n + 2 * k) * 256;
        const __half* Rf1 = Rf0 + 256;

        float4 i4 = add4(add4(ld4h(xp + d),       ld4h(Ri + d)),       bi);
        float4 o4 = add4(add4(ld4h(xp + 256 + d), ld4h(Ri + 256 + d)), bo);
        float4 u4 = add4(add4(ld4h(xp + 512 + d), ld4h(Ri + 512 + d)), bu);
        float4 fx = add4(ld4h(xp + 768 + d), bf);
        float4 f0 = ld4h(Rf0 + d);
        float4 f1 = ld4h(Rf1 + d);

        size_t crow = ((size_t)bb * NNODE + 2 * j + 1) * 256 + d;
        float4 c0 = *(const float4*)(g_c + crow);
        float4 c1 = *(const float4*)(g_c + crow + 256);

        float4 c4, h4;
        c4.x = sigm(i4.x) * tanhf(u4.x) + sigm(fx.x + f0.x) * c0.x + sigm(fx.x + f1.x) * c1.x;
        c4.y = sigm(i4.y) * tanhf(u4.y) + sigm(fx.y + f0.y) * c0.y + sigm(fx.y + f1.y) * c1.y;
        c4.z = sigm(i4.z) * tanhf(u4.z) + sigm(fx.z + f0.z) * c0.z + sigm(fx.z + f1.z) * c1.z;
        c4.w = sigm(i4.w) * tanhf(u4.w) + sigm(fx.w + f0.w) * c0.w + sigm(fx.w + f1.w) * c1.w;
        h4.x = sigm(o4.x) * tanhf(c4.x);
        h4.y = sigm(o4.y) * tanhf(c4.y);
        h4.z = sigm(o4.z) * tanhf(c4.z);
        h4.w = sigm(o4.w) * tanhf(c4.w);

        size_t hrow = row * 256 + d;
        *(float4*)(g_c + hrow) = c4;
        split_store4(g_hh + hrow, g_hl + hrow, h4);
        hs = add4(hs, h4);
    }
    size_t srow = ((size_t)bb * LVH + t) * 256 + d;
    split_store4(g_sh + srow, g_sl + srow, hs);
}

// ---------------- fused small level (n <= 64): one block per parent ----------
__global__ void level_small(const float* __restrict__ b_iou, const float* __restrict__ b_f,
                            const float* __restrict__ U_iou, const float* __restrict__ U_f,
                            int n, float* __restrict__ out) {
    __shared__ float h0s[256], h1s[256], hss[256];
    int blk = blockIdx.x;               // bb * n + k
    int bb = blk / n, k = blk - bb * n;
    int j = n - 1 + k;
    int d = threadIdx.x;

    size_t rc = ((size_t)bb * NNODE + 2 * j + 1) * 256;   // child0 row base
    float h0 = __bfloat162float(g_hh[rc + d]) + __bfloat162float(g_hl[rc + d]);
    float h1 = __bfloat162float(g_hh[rc + 256 + d]) + __bfloat162float(g_hl[rc + 256 + d]);
    h0s[d] = h0; h1s[d] = h1; hss[d] = h0 + h1;
    __syncthreads();

    float ai = 0.f, ao = 0.f, au = 0.f, af0 = 0.f, af1 = 0.f;
#pragma unroll 8
    for (int kk = 0; kk < 256; kk++) {
        float hsv = hss[kk], a0 = h0s[kk], a1 = h1s[kk];
        const float* Ur = U_iou + kk * 768 + d;
        ai = fmaf(hsv, Ur[0], ai);
        ao = fmaf(hsv, Ur[256], ao);
        au = fmaf(hsv, Ur[512], au);
        float wf = U_f[kk * 256 + d];
        af0 = fmaf(a0, wf, af0);
        af1 = fmaf(a1, wf, af1);
    }

    const __half* xp = g_xproj + ((size_t)bb * NNODE + j) * NC;
    float iv = __half2float(xp[d])       + b_iou[d]       + ai;
    float ov = __half2float(xp[256 + d]) + b_iou[256 + d] + ao;
    float uv = __half2float(xp[512 + d]) + b_iou[512 + d] + au;
    float fx = __half2float(xp[768 + d]) + b_f[d];
    float c0 = g_c[rc + d], c1 = g_c[rc + 256 + d];
    float cv = sigm(iv) * tanhf(uv) + sigm(fx + af0) * c0 + sigm(fx + af1) * c1;
    float hv = sigm(ov) * tanhf(cv);

    size_t hrow = ((size_t)bb * NNODE + j) * 256 + d;
    g_c[hrow] = cv;
    __nv_bfloat16 hh = __float2bfloat16_rn(hv);
    g_hh[hrow] = hh;
    g_hl[hrow] = __float2bfloat16_rn(hv - __bfloat162float(hh));

    if (n == 1) {
        out[bb * 512 + d] = hv;
        out[bb * 512 + 256 + d] = cv;
    }
}

// ---------------- launch ----------------------------------------------------
extern "C" void kernel_launch(void* const* d_in, const int* in_sizes, int n_in,
                              void* d_out, int out_size) {
    const float* x     = (const float*)d_in[0];
    const float* W_iou = (const float*)d_in[1];
    const float* b_iou = (const float*)d_in[2];
    const float* U_iou = (const float*)d_in[3];
    const float* W_f   = (const float*)d_in[4];
    const float* b_f   = (const float*)d_in[5];
    const float* U_f   = (const float*)d_in[6];
    float* out = (float*)d_out;

    cudaFuncSetAttribute(gemm_input, cudaFuncAttributeMaxDynamicSharedMemorySize, SMEM_DYN);
    cudaFuncSetAttribute(gemm_rec,   cudaFuncAttributeMaxDynamicSharedMemorySize, SMEM_DYN);

    pack_weights<<<(NC * 256 + 255) / 256, 256>>>(W_iou, W_f, U_iou, U_f);
    {
        size_t n4 = (size_t)TOTAL_ROWS * 256 / 4;
        split_x<<<(unsigned)((n4 + 255) / 256), 256>>>(x);
    }

    // input projection: iou for all rows + f for internal rows (one launch)
    gemm_input<<<6 * TIY_ALL + 2 * TFY_IN, 256, SMEM_DYN>>>();

    // leaves (pairs; also writes h-sum for n=8192)
    leaf_pair<<<BATCH * LVH * 64 / 256, 256>>>(b_iou);

    // big levels: merged iou+f recurrent GEMM (exact flattened grid) + combine
    for (int n = LVH; n >= 128; n >>= 1) {
        int tiy = (8 * n + TBM - 1) / TBM;
        int tfy = (16 * n + TBM - 1) / TBM;
        gemm_rec<<<6 * tiy + 2 * tfy, 256, SMEM_DYN>>>(n);
        int total = BATCH * (n >> 1) * 64;
        combine_pair<<<(total + 255) / 256, 256>>>(b_iou, b_f, n);
    }

    // small levels fused (n = 64 .. 1); n==1 writes out
    for (int n = 64; n >= 1; n >>= 1)
        level_small<<<BATCH * n, 256>>>(b_iou, b_f, U_iou, U_f, n, out);
}